// round 1
// baseline (speedup 1.0000x reference)
#include <cuda_runtime.h>
#include <math.h>

#define NQ     22500
#define GRID_H 150
#define GRID_W 150

// Scratch (no allocations allowed)
__device__ float g_V  [NQ * 256];   // value = query @ W_v + b_v    (nq, 8h*32d)
__device__ float g_OFF[NQ * 128];   // offsets                       (nq, 8h*2qu*4p*2)
__device__ float g_ATT[NQ * 64];    // attn logits                   (nq, 8h*2qu*4p)
__device__ float g_S  [NQ * 256];   // sampled output (mean over queues)

// ----------------------------------------------------------------------------
// Tiled SGEMM: C[M,N] = A @ W + bias (+ ident).
// BM=128, BN=64, BK=16; 256 threads; each thread computes 8x4 outputs.
// QCAT mode: A_logical[m,k] = (k<256) ? A[m*256+k] : A[m*256+k-256]+A2[m*256+k-256]
// ----------------------------------------------------------------------------
template<bool QCAT, bool ADD_ID>
__global__ void __launch_bounds__(256) gemm_kernel(
    const float* __restrict__ A, const float* __restrict__ A2,
    const float* __restrict__ W, const float* __restrict__ bias,
    const float* __restrict__ ident, float* __restrict__ C,
    int M, int N, int K)
{
    const int BM = 128, BN = 64, BK = 16;
    __shared__ __align__(16) float As[BK][BM];
    __shared__ __align__(16) float Bs[BK][BN];

    const int tid = threadIdx.x;
    const int tx  = tid & 15;   // N direction (TN=4)
    const int ty  = tid >> 4;   // M direction (TM=8)
    const int m0  = blockIdx.x * BM;
    const int n0  = blockIdx.y * BN;

    float acc[8][4];
    #pragma unroll
    for (int i = 0; i < 8; i++)
        #pragma unroll
        for (int j = 0; j < 4; j++) acc[i][j] = 0.f;

    for (int k0 = 0; k0 < K; k0 += BK) {
        // --- load A tile (128 rows x 16 cols) as 512 float4, 2 per thread ---
        #pragma unroll
        for (int t = 0; t < 2; t++) {
            int idx = tid + t * 256;
            int row = idx >> 2;
            int c4  = idx & 3;
            int m   = m0 + row;
            int kk  = k0 + c4 * 4;
            float4 v = make_float4(0.f, 0.f, 0.f, 0.f);
            if (m < M) {
                if (QCAT) {
                    int kb = kk & 255;  // BK tile never straddles the 256 boundary
                    v = *(const float4*)(A + (size_t)m * 256 + kb);
                    if (kk >= 256) {
                        float4 v2 = *(const float4*)(A2 + (size_t)m * 256 + kb);
                        v.x += v2.x; v.y += v2.y; v.z += v2.z; v.w += v2.w;
                    }
                } else {
                    v = *(const float4*)(A + (size_t)m * K + kk);
                }
            }
            As[c4 * 4 + 0][row] = v.x;
            As[c4 * 4 + 1][row] = v.y;
            As[c4 * 4 + 2][row] = v.z;
            As[c4 * 4 + 3][row] = v.w;
        }
        // --- load B tile (16 rows x 64 cols) as 256 float4, 1 per thread ---
        {
            int kr = tid >> 4;
            int c4 = tid & 15;
            float4 v = *(const float4*)(W + (size_t)(k0 + kr) * N + n0 + c4 * 4);
            *(float4*)&Bs[kr][c4 * 4] = v;
        }
        __syncthreads();

        #pragma unroll
        for (int k = 0; k < BK; k++) {
            float4 a0 = *(float4*)&As[k][ty * 8];
            float4 a1 = *(float4*)&As[k][ty * 8 + 4];
            float4 b  = *(float4*)&Bs[k][tx * 4];
            float ar[8] = {a0.x, a0.y, a0.z, a0.w, a1.x, a1.y, a1.z, a1.w};
            float br[4] = {b.x, b.y, b.z, b.w};
            #pragma unroll
            for (int i = 0; i < 8; i++)
                #pragma unroll
                for (int j = 0; j < 4; j++)
                    acc[i][j] += ar[i] * br[j];
        }
        __syncthreads();
    }

    float4 bv = *(const float4*)(bias + n0 + tx * 4);
    #pragma unroll
    for (int i = 0; i < 8; i++) {
        int m = m0 + ty * 8 + i;
        if (m < M) {
            float4 o;
            o.x = acc[i][0] + bv.x;
            o.y = acc[i][1] + bv.y;
            o.z = acc[i][2] + bv.z;
            o.w = acc[i][3] + bv.w;
            if (ADD_ID) {
                float4 id = *(const float4*)(ident + (size_t)m * N + n0 + tx * 4);
                o.x += id.x; o.y += id.y; o.z += id.z; o.w += id.w;
            }
            *(float4*)(C + (size_t)m * N + n0 + tx * 4) = o;
        }
    }
}

// ----------------------------------------------------------------------------
// Deformable sampling. One block per query, one warp per head, one lane per
// channel. Accumulates over 2 queues x 4 points x 4 bilinear taps; output is
// the queue-mean (x0.5).
// ----------------------------------------------------------------------------
__device__ __forceinline__ float tap(const float* __restrict__ V,
                                     int x, int y, int ch) {
    if (x < 0 || x >= GRID_W || y < 0 || y >= GRID_H) return 0.f;
    return __ldg(V + ((size_t)y * GRID_W + x) * 256 + ch);
}

__global__ void __launch_bounds__(256) sample_kernel(
    const float* __restrict__ V, const float* __restrict__ OFF,
    const float* __restrict__ ATT, const float* __restrict__ RP,
    float* __restrict__ S)
{
    const int q    = blockIdx.x;
    const int h    = threadIdx.x >> 5;  // head (warp id)
    const int lane = threadIdx.x & 31;  // channel within head
    const int ch   = h * 32 + lane;

    const float* att = ATT + (size_t)q * 64 + h * 8;    // [queue][point]
    const float* off = OFF + (size_t)q * 128 + h * 16;  // [queue][point][2]

    float acc = 0.f;
    #pragma unroll
    for (int qu = 0; qu < 2; qu++) {
        // softmax over 4 points
        float l0 = att[qu * 4 + 0], l1 = att[qu * 4 + 1];
        float l2 = att[qu * 4 + 2], l3 = att[qu * 4 + 3];
        float mx = fmaxf(fmaxf(l0, l1), fmaxf(l2, l3));
        float e0 = expf(l0 - mx), e1 = expf(l1 - mx);
        float e2 = expf(l2 - mx), e3 = expf(l3 - mx);
        float inv = 1.f / (e0 + e1 + e2 + e3);
        float w[4] = {e0 * inv, e1 * inv, e2 * inv, e3 * inv};

        float rpx = RP[(size_t)qu * NQ * 2 + (size_t)q * 2 + 0];
        float rpy = RP[(size_t)qu * NQ * 2 + (size_t)q * 2 + 1];

        #pragma unroll
        for (int p = 0; p < 4; p++) {
            float ox = off[qu * 8 + p * 2 + 0];
            float oy = off[qu * 8 + p * 2 + 1];
            float locx = rpx + ox * (1.f / GRID_W);
            float locy = rpy + oy * (1.f / GRID_H);
            float x = locx * GRID_W - 0.5f;
            float y = locy * GRID_H - 0.5f;
            float x0f = floorf(x), y0f = floorf(y);
            float wx = x - x0f, wy = y - y0f;
            int x0 = (int)x0f, y0 = (int)y0f;
            float aw = w[p];
            acc += tap(V, x0,     y0,     ch) * (aw * (1.f - wx) * (1.f - wy));
            acc += tap(V, x0 + 1, y0,     ch) * (aw * wx         * (1.f - wy));
            acc += tap(V, x0,     y0 + 1, ch) * (aw * (1.f - wx) * wy);
            acc += tap(V, x0 + 1, y0 + 1, ch) * (aw * wx         * wy);
        }
    }
    S[(size_t)q * 256 + ch] = acc * 0.5f;  // mean over the 2 queues
}

// ----------------------------------------------------------------------------
extern "C" void kernel_launch(void* const* d_in, const int* in_sizes, int n_in,
                              void* d_out, int out_size)
{
    const float* query  = (const float*)d_in[0];
    const float* qpos   = (const float*)d_in[1];
    const float* rp     = (const float*)d_in[2];
    const float* W_off  = (const float*)d_in[3];
    const float* b_off  = (const float*)d_in[4];
    const float* W_attn = (const float*)d_in[5];
    const float* b_attn = (const float*)d_in[6];
    const float* W_v    = (const float*)d_in[7];
    const float* b_v    = (const float*)d_in[8];
    const float* W_out  = (const float*)d_in[9];
    const float* b_out  = (const float*)d_in[10];
    float* out = (float*)d_out;

    float *V, *OFF, *ATT, *S;
    cudaGetSymbolAddress((void**)&V,   g_V);
    cudaGetSymbolAddress((void**)&OFF, g_OFF);
    cudaGetSymbolAddress((void**)&ATT, g_ATT);
    cudaGetSymbolAddress((void**)&S,   g_S);

    const int MB = (NQ + 127) / 128;  // 176
    dim3 blk(256);

    // value = query @ W_v + b_v  (both queues identical -> compute once)
    gemm_kernel<false, false><<<dim3(MB, 4), blk>>>(query, nullptr, W_v, b_v,
                                                    nullptr, V, NQ, 256, 256);
    // off = [query, query+qpos] @ W_off + b_off
    gemm_kernel<true, false><<<dim3(MB, 2), blk>>>(query, qpos, W_off, b_off,
                                                   nullptr, OFF, NQ, 128, 512);
    // attn logits = [query, query+qpos] @ W_attn + b_attn
    gemm_kernel<true, false><<<dim3(MB, 1), blk>>>(query, qpos, W_attn, b_attn,
                                                   nullptr, ATT, NQ, 64, 512);
    // deformable bilinear sampling + softmax + queue-mean
    sample_kernel<<<NQ, 256>>>(V, OFF, ATT, rp, S);
    // out = S @ W_out + b_out + query (residual)
    gemm_kernel<false, true><<<dim3(MB, 4), blk>>>(S, nullptr, W_out, b_out,
                                                   query, out, NQ, 256, 256);
}

// round 2
// speedup vs baseline: 1.9395x; 1.9395x over previous
#include <cuda_runtime.h>
#include <cuda_bf16.h>
#include <math.h>
#include <stdint.h>

#define NQ     22500
#define GRID_H 150
#define GRID_W 150

// Scratch (no allocations allowed)
__device__ float g_V  [NQ * 256];   // value = query @ W_v + b_v    (nq, 8h*32d)
__device__ float g_OFF[NQ * 128];   // offsets                       (nq, 8h*2qu*4p*2)
__device__ float g_ATT[NQ * 64];    // attn logits                   (nq, 8h*2qu*4p)
__device__ float g_S  [NQ * 256];   // sampled output (mean over queues)

// ----------------------------------------------------------------------------
// bf16x3 tensor-core GEMM: C[M,N] = A @ W + bias (+ ident), fp32-grade accuracy.
// Each fp32 operand split into hi+lo bf16; C += Ahi*Bhi + Ahi*Blo + Alo*Bhi.
// BM=128, BN=64, BK=32. 256 threads = 8 warps laid out 4(m) x 2(n).
// Each warp owns a 32x32 patch = 2 m16-tiles x 4 n8-tiles of m16n8k16 MMAs.
// QCAT: A_logical[m,k] = (k<256) ? A[m,k] : A[m,k-256] + A2[m,k-256]  (K=512)
// ----------------------------------------------------------------------------

__device__ __forceinline__ uint32_t smem_u32(const void* p) {
    return (uint32_t)__cvta_generic_to_shared(p);
}

__device__ __forceinline__ void ldsm_x4(uint32_t* r, uint32_t addr) {
    asm volatile("ldmatrix.sync.aligned.m8n8.x4.shared.b16 {%0,%1,%2,%3}, [%4];"
                 : "=r"(r[0]), "=r"(r[1]), "=r"(r[2]), "=r"(r[3]) : "r"(addr));
}
__device__ __forceinline__ void ldsm_x2_t(uint32_t* r, uint32_t addr) {
    asm volatile("ldmatrix.sync.aligned.m8n8.x2.trans.shared.b16 {%0,%1}, [%2];"
                 : "=r"(r[0]), "=r"(r[1]) : "r"(addr));
}
__device__ __forceinline__ void mma_bf16(float* c, const uint32_t* a, const uint32_t* b) {
    asm volatile(
        "mma.sync.aligned.m16n8k16.row.col.f32.bf16.bf16.f32 "
        "{%0,%1,%2,%3}, {%4,%5,%6,%7}, {%8,%9}, {%0,%1,%2,%3};"
        : "+f"(c[0]), "+f"(c[1]), "+f"(c[2]), "+f"(c[3])
        : "r"(a[0]), "r"(a[1]), "r"(a[2]), "r"(a[3]), "r"(b[0]), "r"(b[1]));
}

// split a float4 into hi/lo bf16x4 (8 bytes each) and store
__device__ __forceinline__ void split_store(__nv_bfloat16* hp, __nv_bfloat16* lp,
                                            float4 v) {
    union U { __nv_bfloat162 h2[2]; uint2 u; };
    U uh, ul;
    uh.h2[0] = __floats2bfloat162_rn(v.x, v.y);
    uh.h2[1] = __floats2bfloat162_rn(v.z, v.w);
    float rx = v.x - __bfloat162float(uh.h2[0].x);
    float ry = v.y - __bfloat162float(uh.h2[0].y);
    float rz = v.z - __bfloat162float(uh.h2[1].x);
    float rw = v.w - __bfloat162float(uh.h2[1].y);
    ul.h2[0] = __floats2bfloat162_rn(rx, ry);
    ul.h2[1] = __floats2bfloat162_rn(rz, rw);
    *(uint2*)hp = uh.u;
    *(uint2*)lp = ul.u;
}

#define AS_STRIDE 40   // bf16 units (80B rows: conflict-free ldmatrix phases)
#define BS_STRIDE 72   // bf16 units (144B rows: conflict-free ldmatrix.trans)

template<bool QCAT, bool ADD_ID>
__global__ void __launch_bounds__(256) mma_gemm(
    const float* __restrict__ A, const float* __restrict__ A2,
    const float* __restrict__ W, const float* __restrict__ bias,
    const float* __restrict__ ident, float* __restrict__ C,
    int M, int N, int K)
{
    __shared__ __nv_bfloat16 As_hi[128 * AS_STRIDE];
    __shared__ __nv_bfloat16 As_lo[128 * AS_STRIDE];
    __shared__ __nv_bfloat16 Bs_hi[32 * BS_STRIDE];
    __shared__ __nv_bfloat16 Bs_lo[32 * BS_STRIDE];

    const int tid  = threadIdx.x;
    const int lane = tid & 31;
    const int warp = tid >> 5;
    const int warp_m = warp & 3;   // 4 slices of 32 rows
    const int warp_n = warp >> 2;  // 2 slices of 32 cols
    const int m0 = blockIdx.x * 128;
    const int n0 = blockIdx.y * 64;

    float c[2][4][4];
    #pragma unroll
    for (int i = 0; i < 2; i++)
        #pragma unroll
        for (int j = 0; j < 4; j++)
            #pragma unroll
            for (int k = 0; k < 4; k++) c[i][j][k] = 0.f;

    float4 aS[4], bS[2];

    // ---- global loads into staging registers (guarded on M tail) ----
    auto loadA = [&](int k0) {
        #pragma unroll
        for (int i = 0; i < 4; i++) {
            int idx = i * 256 + tid;
            int row = idx >> 3;        // 0..127
            int kk  = (idx & 7) * 4;   // 0..28
            int m   = m0 + row;
            float4 v = make_float4(0.f, 0.f, 0.f, 0.f);
            if (m < M) {
                int kg = k0 + kk;
                if (QCAT) {
                    int kb = kg & 255;
                    v = *(const float4*)(A + (size_t)m * 256 + kb);
                    if (kg >= 256) {
                        float4 w2 = *(const float4*)(A2 + (size_t)m * 256 + kb);
                        v.x += w2.x; v.y += w2.y; v.z += w2.z; v.w += w2.w;
                    }
                } else {
                    v = *(const float4*)(A + (size_t)m * K + kg);
                }
            }
            aS[i] = v;
        }
    };
    auto loadB = [&](int k0) {
        #pragma unroll
        for (int i = 0; i < 2; i++) {
            int idx = i * 256 + tid;
            int row = idx >> 4;        // k within tile, 0..31
            int nn  = (idx & 15) * 4;  // 0..60
            bS[i] = *(const float4*)(W + (size_t)(k0 + row) * N + n0 + nn);
        }
    };
    auto storeS = [&]() {
        #pragma unroll
        for (int i = 0; i < 4; i++) {
            int idx = i * 256 + tid;
            int row = idx >> 3;
            int kk  = (idx & 7) * 4;
            split_store(&As_hi[row * AS_STRIDE + kk], &As_lo[row * AS_STRIDE + kk], aS[i]);
        }
        #pragma unroll
        for (int i = 0; i < 2; i++) {
            int idx = i * 256 + tid;
            int row = idx >> 4;
            int nn  = (idx & 15) * 4;
            split_store(&Bs_hi[row * BS_STRIDE + nn], &Bs_lo[row * BS_STRIDE + nn], bS[i]);
        }
    };

    // ---- ldmatrix lane addressing ----
    // A x4: quad q=lane>>3: rows mbase+(lane&7)+(q&1)*8, cols k16*16+(q>>1)*8
    const int a_r_off = (lane & 7) + ((lane >> 3) & 1) * 8;
    const int a_k_off = ((lane >> 4) & 1) * 8;
    // B x2.trans: rows k16*16 + (lane&7) + ((lane>>3)&1)*8 (lanes >=16 ignored)
    const int b_k_off = (lane & 7) + ((lane >> 3) & 1) * 8;

    auto mmaTile = [&]() {
        #pragma unroll
        for (int k16 = 0; k16 < 2; k16++) {
            uint32_t ahi[2][4], alo[2][4];
            #pragma unroll
            for (int mt = 0; mt < 2; mt++) {
                int r  = warp_m * 32 + mt * 16 + a_r_off;
                int kc = k16 * 16 + a_k_off;
                ldsm_x4(ahi[mt], smem_u32(&As_hi[r * AS_STRIDE + kc]));
                ldsm_x4(alo[mt], smem_u32(&As_lo[r * AS_STRIDE + kc]));
            }
            #pragma unroll
            for (int nt = 0; nt < 4; nt++) {
                int nb = warp_n * 32 + nt * 8;
                int kr = k16 * 16 + b_k_off;
                uint32_t bhi[2], blo[2];
                ldsm_x2_t(bhi, smem_u32(&Bs_hi[kr * BS_STRIDE + nb]));
                ldsm_x2_t(blo, smem_u32(&Bs_lo[kr * BS_STRIDE + nb]));
                #pragma unroll
                for (int mt = 0; mt < 2; mt++) {
                    mma_bf16(c[mt][nt], ahi[mt], bhi);
                    mma_bf16(c[mt][nt], ahi[mt], blo);
                    mma_bf16(c[mt][nt], alo[mt], bhi);
                }
            }
        }
    };

    const int T = K / 32;
    loadA(0); loadB(0);
    for (int t = 0; t < T; t++) {
        __syncthreads();   // previous tile's MMA reads complete before overwrite
        storeS();
        __syncthreads();
        if (t + 1 < T) { loadA((t + 1) * 32); loadB((t + 1) * 32); }
        mmaTile();
    }

    // ---- epilogue ----
    const int gid = lane >> 2, tig = lane & 3;
    #pragma unroll
    for (int mt = 0; mt < 2; mt++) {
        #pragma unroll
        for (int nt = 0; nt < 4; nt++) {
            int r0 = m0 + warp_m * 32 + mt * 16 + gid;
            int cc = n0 + warp_n * 32 + nt * 8 + tig * 2;
            float b0 = bias[cc], b1 = bias[cc + 1];
            if (r0 < M) {
                float2 o = make_float2(c[mt][nt][0] + b0, c[mt][nt][1] + b1);
                if (ADD_ID) {
                    float2 id = *(const float2*)(ident + (size_t)r0 * N + cc);
                    o.x += id.x; o.y += id.y;
                }
                *(float2*)(C + (size_t)r0 * N + cc) = o;
            }
            int r1 = r0 + 8;
            if (r1 < M) {
                float2 o = make_float2(c[mt][nt][2] + b0, c[mt][nt][3] + b1);
                if (ADD_ID) {
                    float2 id = *(const float2*)(ident + (size_t)r1 * N + cc);
                    o.x += id.x; o.y += id.y;
                }
                *(float2*)(C + (size_t)r1 * N + cc) = o;
            }
        }
    }
}

// ----------------------------------------------------------------------------
// Deformable sampling, vectorized: each thread owns 4 channels (float4 taps).
// 64 threads per query (8 heads x 8 channel-groups); 4 queries per 256-thr block.
// ----------------------------------------------------------------------------
__global__ void __launch_bounds__(256) sample_kernel(
    const float* __restrict__ V, const float* __restrict__ OFF,
    const float* __restrict__ ATT, const float* __restrict__ RP,
    float* __restrict__ S)
{
    const int q   = blockIdx.x * 4 + (threadIdx.x >> 6);
    const int loc = threadIdx.x & 63;
    const int h   = loc >> 3;          // head
    const int c4  = loc & 7;           // channel group
    const int ch0 = h * 32 + c4 * 4;

    const float* att = ATT + (size_t)q * 64 + h * 8;    // [queue][point]
    const float* off = OFF + (size_t)q * 128 + h * 16;  // [queue][point][2]

    float4 acc = make_float4(0.f, 0.f, 0.f, 0.f);
    #pragma unroll
    for (int qu = 0; qu < 2; qu++) {
        float l0 = att[qu * 4 + 0], l1 = att[qu * 4 + 1];
        float l2 = att[qu * 4 + 2], l3 = att[qu * 4 + 3];
        float mx = fmaxf(fmaxf(l0, l1), fmaxf(l2, l3));
        float e0 = __expf(l0 - mx), e1 = __expf(l1 - mx);
        float e2 = __expf(l2 - mx), e3 = __expf(l3 - mx);
        float inv = 1.f / (e0 + e1 + e2 + e3);
        float w[4] = {e0 * inv, e1 * inv, e2 * inv, e3 * inv};

        float rpx = RP[(size_t)qu * NQ * 2 + (size_t)q * 2 + 0];
        float rpy = RP[(size_t)qu * NQ * 2 + (size_t)q * 2 + 1];

        #pragma unroll
        for (int p = 0; p < 4; p++) {
            float ox = off[qu * 8 + p * 2 + 0];
            float oy = off[qu * 8 + p * 2 + 1];
            float x = (rpx + ox * (1.f / GRID_W)) * GRID_W - 0.5f;
            float y = (rpy + oy * (1.f / GRID_H)) * GRID_H - 0.5f;
            float x0f = floorf(x), y0f = floorf(y);
            float wx = x - x0f, wy = y - y0f;
            int x0 = (int)x0f, y0 = (int)y0f;
            float aw = w[p];
            float tw[4] = {aw * (1.f - wx) * (1.f - wy), aw * wx * (1.f - wy),
                           aw * (1.f - wx) * wy,          aw * wx * wy};
            int xs[4] = {x0, x0 + 1, x0,     x0 + 1};
            int ys[4] = {y0, y0,     y0 + 1, y0 + 1};
            #pragma unroll
            for (int t = 0; t < 4; t++) {
                int xx = xs[t], yy = ys[t];
                if (xx >= 0 && xx < GRID_W && yy >= 0 && yy < GRID_H) {
                    float4 v = __ldg((const float4*)(V +
                        ((size_t)yy * GRID_W + xx) * 256 + ch0));
                    float wt = tw[t];
                    acc.x += v.x * wt; acc.y += v.y * wt;
                    acc.z += v.z * wt; acc.w += v.w * wt;
                }
            }
        }
    }
    acc.x *= 0.5f; acc.y *= 0.5f; acc.z *= 0.5f; acc.w *= 0.5f;
    *(float4*)(S + (size_t)q * 256 + ch0) = acc;
}

// ----------------------------------------------------------------------------
extern "C" void kernel_launch(void* const* d_in, const int* in_sizes, int n_in,
                              void* d_out, int out_size)
{
    const float* query  = (const float*)d_in[0];
    const float* qpos   = (const float*)d_in[1];
    const float* rp     = (const float*)d_in[2];
    const float* W_off  = (const float*)d_in[3];
    const float* b_off  = (const float*)d_in[4];
    const float* W_attn = (const float*)d_in[5];
    const float* b_attn = (const float*)d_in[6];
    const float* W_v    = (const float*)d_in[7];
    const float* b_v    = (const float*)d_in[8];
    const float* W_out  = (const float*)d_in[9];
    const float* b_out  = (const float*)d_in[10];
    float* out = (float*)d_out;

    float *V, *OFF, *ATT, *S;
    cudaGetSymbolAddress((void**)&V,   g_V);
    cudaGetSymbolAddress((void**)&OFF, g_OFF);
    cudaGetSymbolAddress((void**)&ATT, g_ATT);
    cudaGetSymbolAddress((void**)&S,   g_S);

    const int MB = (NQ + 127) / 128;  // 176
    dim3 blk(256);

    // value = query @ W_v + b_v  (both queues identical -> compute once)
    mma_gemm<false, false><<<dim3(MB, 4), blk>>>(query, nullptr, W_v, b_v,
                                                 nullptr, V, NQ, 256, 256);
    // off = [query, query+qpos] @ W_off + b_off
    mma_gemm<true, false><<<dim3(MB, 2), blk>>>(query, qpos, W_off, b_off,
                                                nullptr, OFF, NQ, 128, 512);
    // attn logits = [query, query+qpos] @ W_attn + b_attn
    mma_gemm<true, false><<<dim3(MB, 1), blk>>>(query, qpos, W_attn, b_attn,
                                                nullptr, ATT, NQ, 64, 512);
    // deformable bilinear sampling + softmax + queue-mean
    sample_kernel<<<NQ / 4, blk>>>(V, OFF, ATT, rp, S);
    // out = S @ W_out + b_out + query (residual)
    mma_gemm<false, true><<<dim3(MB, 4), blk>>>(S, nullptr, W_out, b_out,
                                                query, out, NQ, 256, 256);
}

// round 4
// speedup vs baseline: 2.9102x; 1.5005x over previous
#include <cuda_runtime.h>
#include <cuda_bf16.h>
#include <math.h>
#include <stdint.h>

#define NQ     22500
#define GRID_H 150
#define GRID_W 150

// ---------------- scratch (no allocations allowed) ----------------
__device__ __nv_bfloat16 g_Aq  [NQ * 512];    // [hi(q) | lo(q)]           K'=512
__device__ __nv_bfloat16 g_Aqc [NQ * 1024];   // [hi(q),hi(q+p)|lo(q),lo(q+p)] K'=1024
__device__ __nv_bfloat16 g_Ssp [NQ * 512];    // [hi(S) | lo(S)]           K'=512
__device__ float         g_V   [NQ * 256];    // value (fp32, for sampler)
__device__ float         g_OFF [NQ * 128];
__device__ float         g_ATT [NQ * 64];
__device__ __nv_bfloat16 g_Wv  [512  * 256];  // split weights (hi rows 0..K-1, lo rows K..2K-1)
__device__ __nv_bfloat16 g_Woff[1024 * 128];
__device__ __nv_bfloat16 g_Watt[1024 * 64];
__device__ __nv_bfloat16 g_Wout[512  * 256];

// ---------------- helpers ----------------
__device__ __forceinline__ uint32_t smem_u32(const void* p) {
    return (uint32_t)__cvta_generic_to_shared(p);
}
__device__ __forceinline__ void ldsm_x4(uint32_t* r, uint32_t addr) {
    asm volatile("ldmatrix.sync.aligned.m8n8.x4.shared.b16 {%0,%1,%2,%3}, [%4];"
                 : "=r"(r[0]), "=r"(r[1]), "=r"(r[2]), "=r"(r[3]) : "r"(addr));
}
__device__ __forceinline__ void ldsm_x4_t(uint32_t* r, uint32_t addr) {
    asm volatile("ldmatrix.sync.aligned.m8n8.x4.trans.shared.b16 {%0,%1,%2,%3}, [%4];"
                 : "=r"(r[0]), "=r"(r[1]), "=r"(r[2]), "=r"(r[3]) : "r"(addr));
}
__device__ __forceinline__ void mma_bf16(float* c, const uint32_t* a, const uint32_t* b) {
    asm volatile(
        "mma.sync.aligned.m16n8k16.row.col.f32.bf16.bf16.f32 "
        "{%0,%1,%2,%3}, {%4,%5,%6,%7}, {%8,%9}, {%0,%1,%2,%3};"
        : "+f"(c[0]), "+f"(c[1]), "+f"(c[2]), "+f"(c[3])
        : "r"(a[0]), "r"(a[1]), "r"(a[2]), "r"(a[3]), "r"(b[0]), "r"(b[1]));
}
__device__ __forceinline__ void cp16(void* smem, const void* gmem, bool pred) {
    int sz = pred ? 16 : 0;
    asm volatile("cp.async.cg.shared.global [%0], [%1], 16, %2;"
                 :: "r"(smem_u32(smem)), "l"(gmem), "r"(sz) : "memory");
}
__device__ __forceinline__ void cp_commit() {
    asm volatile("cp.async.commit_group;" ::: "memory");
}
template<int N> __device__ __forceinline__ void cp_wait() {
    asm volatile("cp.async.wait_group %0;" :: "n"(N) : "memory");
}

// split float4 into hi/lo bf16x4 (packed as uint2 each)
__device__ __forceinline__ void split4(float4 v, uint2& h, uint2& l) {
    union U { __nv_bfloat162 b[2]; uint2 u; };
    U uh, ul;
    uh.b[0] = __floats2bfloat162_rn(v.x, v.y);
    uh.b[1] = __floats2bfloat162_rn(v.z, v.w);
    ul.b[0] = __floats2bfloat162_rn(v.x - __bfloat162float(uh.b[0].x),
                                    v.y - __bfloat162float(uh.b[0].y));
    ul.b[1] = __floats2bfloat162_rn(v.z - __bfloat162float(uh.b[1].x),
                                    v.w - __bfloat162float(uh.b[1].y));
    h = uh.u; l = ul.u;
}

// ---------------- split kernels ----------------
__global__ void __launch_bounds__(256) split_qcat(const float* __restrict__ q,
                                                  const float* __restrict__ qp) {
    int idx = blockIdx.x * 256 + threadIdx.x;       // NQ*64 threads
    int m = idx >> 6;
    int c = (idx & 63) * 4;
    float4 qv = *(const float4*)(q  + (size_t)m * 256 + c);
    float4 pv = *(const float4*)(qp + (size_t)m * 256 + c);
    float4 sv = make_float4(qv.x + pv.x, qv.y + pv.y, qv.z + pv.z, qv.w + pv.w);
    uint2 qh, ql, sh, sl;
    split4(qv, qh, ql);
    split4(sv, sh, sl);
    *(uint2*)&g_Aq [(size_t)m * 512  + c]        = qh;
    *(uint2*)&g_Aq [(size_t)m * 512  + 256 + c]  = ql;
    *(uint2*)&g_Aqc[(size_t)m * 1024 + c]        = qh;
    *(uint2*)&g_Aqc[(size_t)m * 1024 + 256 + c]  = sh;
    *(uint2*)&g_Aqc[(size_t)m * 1024 + 512 + c]  = ql;
    *(uint2*)&g_Aqc[(size_t)m * 1024 + 768 + c]  = sl;
}

__global__ void __launch_bounds__(256) split_w(const float* __restrict__ Wv,
                                               const float* __restrict__ Woff,
                                               const float* __restrict__ Watt,
                                               const float* __restrict__ Wout) {
    int idx = blockIdx.x * 256 + threadIdx.x;       // 57344 float4 slots
    const float* src; __nv_bfloat16* dst; int K, N, e;
    if      (idx < 16384) { src = Wv;   dst = g_Wv;   K = 256; N = 256; e = idx;         }
    else if (idx < 32768) { src = Woff; dst = g_Woff; K = 512; N = 128; e = idx - 16384; }
    else if (idx < 40960) { src = Watt; dst = g_Watt; K = 512; N = 64;  e = idx - 32768; }
    else                  { src = Wout; dst = g_Wout; K = 256; N = 256; e = idx - 40960; }
    int n4 = N / 4;
    int k = e / n4;
    int n = (e % n4) * 4;
    float4 v = *(const float4*)(src + (size_t)k * N + n);
    uint2 h, l;
    split4(v, h, l);
    *(uint2*)&dst[(size_t)k * N + n]       = h;
    *(uint2*)&dst[(size_t)(K + k) * N + n] = l;
}

// ----------------------------------------------------------------------------
// bf16 tensor-core GEMM over pre-split operands (K' = 2K gives fp32 accuracy).
// BM=128, BN=64, BK=64. 256 threads = 8 warps (4m x 2n), warp tile 32x32.
// cp.async double-buffered smem with SW128 swizzle (conflict-free ldmatrix).
// ----------------------------------------------------------------------------
template<bool ADD_ID>
__global__ void __launch_bounds__(256) mma_gemm(
    const __nv_bfloat16* __restrict__ A, const __nv_bfloat16* __restrict__ B,
    const float* __restrict__ bias, const float* __restrict__ ident,
    float* __restrict__ C, int M, int N, int K2)
{
    __shared__ __nv_bfloat16 Asm[2][128 * 64];   // 128 rows x 128B (swizzled)
    __shared__ __nv_bfloat16 Bsm[2][64 * 64];    // 64 k-rows x 128B (swizzled)

    const int tid  = threadIdx.x;
    const int lane = tid & 31;
    const int warp = tid >> 5;
    const int warp_m = warp & 3;
    const int warp_n = warp >> 2;
    const int m0 = blockIdx.x * 128;
    const int n0 = blockIdx.y * 64;

    float c[2][4][4];
    #pragma unroll
    for (int i = 0; i < 2; i++)
        #pragma unroll
        for (int j = 0; j < 4; j++)
            #pragma unroll
            for (int k = 0; k < 4; k++) c[i][j][k] = 0.f;

    auto issue = [&](int t, int s) {
        // A tile: 128 rows x 8 16B-chunks = 1024 chunks
        #pragma unroll
        for (int i = 0; i < 4; i++) {
            int idx = i * 256 + tid;
            int r = idx >> 3, u = idx & 7;
            int m = m0 + r;
            const void* src = A + (size_t)(m < M ? m : M - 1) * K2 + t * 64 + u * 8;
            void* dst = (char*)Asm[s] + r * 128 + ((u ^ (r & 7)) << 4);
            cp16(dst, src, m < M);
        }
        // B tile: 64 rows x 8 chunks = 512 chunks
        #pragma unroll
        for (int i = 0; i < 2; i++) {
            int idx = i * 256 + tid;
            int r = idx >> 3, u = idx & 7;
            const void* src = B + (size_t)(t * 64 + r) * N + n0 + u * 8;
            void* dst = (char*)Bsm[s] + r * 128 + ((u ^ (r & 7)) << 4);
            cp16(dst, src, true);
        }
        cp_commit();
    };

    const int a_r_base = (lane & 7) + ((lane >> 3) & 1) * 8;
    const int a_u      = (lane >> 4) & 1;
    const int b_r_base = (lane & 7) + ((lane >> 3) & 1) * 8;
    const int b_u      = (lane >> 4) & 1;

    auto mmaTile = [&](int s) {
        const char* Ab = (const char*)Asm[s];
        const char* Bb = (const char*)Bsm[s];
        #pragma unroll
        for (int k16 = 0; k16 < 4; k16++) {
            uint32_t a[2][4];
            #pragma unroll
            for (int mt = 0; mt < 2; mt++) {
                int r = warp_m * 32 + mt * 16 + a_r_base;
                int u = k16 * 2 + a_u;
                ldsm_x4(a[mt], smem_u32(Ab + r * 128 + ((u ^ (r & 7)) << 4)));
            }
            uint32_t b[4][2];
            #pragma unroll
            for (int ntp = 0; ntp < 2; ntp++) {
                int kr = k16 * 16 + b_r_base;
                int u  = warp_n * 4 + ntp * 2 + b_u;
                uint32_t rr[4];
                ldsm_x4_t(rr, smem_u32(Bb + kr * 128 + ((u ^ (kr & 7)) << 4)));
                b[ntp * 2][0] = rr[0]; b[ntp * 2][1] = rr[1];
                b[ntp * 2 + 1][0] = rr[2]; b[ntp * 2 + 1][1] = rr[3];
            }
            #pragma unroll
            for (int nt = 0; nt < 4; nt++)
                #pragma unroll
                for (int mt = 0; mt < 2; mt++)
                    mma_bf16(c[mt][nt], a[mt], b[nt]);
        }
    };

    const int T = K2 >> 6;
    issue(0, 0);
    for (int t = 0; t < T; t++) {
        int s = t & 1;
        if (t + 1 < T) issue(t + 1, s ^ 1);
        if (t + 1 < T) cp_wait<1>(); else cp_wait<0>();
        __syncthreads();
        mmaTile(s);
        __syncthreads();   // all warps done reading buf s before it is refilled
    }

    // epilogue
    const int gid = lane >> 2, tig = lane & 3;
    #pragma unroll
    for (int mt = 0; mt < 2; mt++) {
        #pragma unroll
        for (int nt = 0; nt < 4; nt++) {
            int r0 = m0 + warp_m * 32 + mt * 16 + gid;
            int cc = n0 + warp_n * 32 + nt * 8 + tig * 2;
            float b0 = bias[cc], b1 = bias[cc + 1];
            if (r0 < M) {
                float2 o = make_float2(c[mt][nt][0] + b0, c[mt][nt][1] + b1);
                if (ADD_ID) {
                    float2 id = *(const float2*)(ident + (size_t)r0 * N + cc);
                    o.x += id.x; o.y += id.y;
                }
                *(float2*)(C + (size_t)r0 * N + cc) = o;
            }
            int r1 = r0 + 8;
            if (r1 < M) {
                float2 o = make_float2(c[mt][nt][2] + b0, c[mt][nt][3] + b1);
                if (ADD_ID) {
                    float2 id = *(const float2*)(ident + (size_t)r1 * N + cc);
                    o.x += id.x; o.y += id.y;
                }
                *(float2*)(C + (size_t)r1 * N + cc) = o;
            }
        }
    }
}

// ----------------------------------------------------------------------------
// Deformable sampling (float4 per thread). Writes S pre-split into bf16 hi/lo
// so the output GEMM consumes it directly.
// ----------------------------------------------------------------------------
__global__ void __launch_bounds__(256) sample_kernel(
    const float* __restrict__ V, const float* __restrict__ OFF,
    const float* __restrict__ ATT, const float* __restrict__ RP)
{
    const int q   = blockIdx.x * 4 + (threadIdx.x >> 6);
    const int loc = threadIdx.x & 63;
    const int h   = loc >> 3;
    const int c4  = loc & 7;
    const int ch0 = h * 32 + c4 * 4;

    const float* att = ATT + (size_t)q * 64 + h * 8;
    const float* off = OFF + (size_t)q * 128 + h * 16;

    float4 acc = make_float4(0.f, 0.f, 0.f, 0.f);
    #pragma unroll
    for (int qu = 0; qu < 2; qu++) {
        float l0 = att[qu * 4 + 0], l1 = att[qu * 4 + 1];
        float l2 = att[qu * 4 + 2], l3 = att[qu * 4 + 3];
        float mx = fmaxf(fmaxf(l0, l1), fmaxf(l2, l3));
        float e0 = __expf(l0 - mx), e1 = __expf(l1 - mx);
        float e2 = __expf(l2 - mx), e3 = __expf(l3 - mx);
        float inv = 1.f / (e0 + e1 + e2 + e3);
        float w[4] = {e0 * inv, e1 * inv, e2 * inv, e3 * inv};

        float rpx = RP[(size_t)qu * NQ * 2 + (size_t)q * 2 + 0];
        float rpy = RP[(size_t)qu * NQ * 2 + (size_t)q * 2 + 1];

        #pragma unroll
        for (int p = 0; p < 4; p++) {
            float ox = off[qu * 8 + p * 2 + 0];
            float oy = off[qu * 8 + p * 2 + 1];
            float x = (rpx + ox * (1.f / GRID_W)) * GRID_W - 0.5f;
            float y = (rpy + oy * (1.f / GRID_H)) * GRID_H - 0.5f;
            float x0f = floorf(x), y0f = floorf(y);
            float wx = x - x0f, wy = y - y0f;
            int x0 = (int)x0f, y0 = (int)y0f;
            float aw = w[p];
            float tw[4] = {aw * (1.f - wx) * (1.f - wy), aw * wx * (1.f - wy),
                           aw * (1.f - wx) * wy,          aw * wx * wy};
            int xs[4] = {x0, x0 + 1, x0,     x0 + 1};
            int ys[4] = {y0, y0,     y0 + 1, y0 + 1};
            #pragma unroll
            for (int t = 0; t < 4; t++) {
                int xx = xs[t], yy = ys[t];
                if (xx >= 0 && xx < GRID_W && yy >= 0 && yy < GRID_H) {
                    float4 v = __ldg((const float4*)(V +
                        ((size_t)yy * GRID_W + xx) * 256 + ch0));
                    float wt = tw[t];
                    acc.x += v.x * wt; acc.y += v.y * wt;
                    acc.z += v.z * wt; acc.w += v.w * wt;
                }
            }
        }
    }
    acc.x *= 0.5f; acc.y *= 0.5f; acc.z *= 0.5f; acc.w *= 0.5f;
    uint2 h2, l2v;
    split4(acc, h2, l2v);
    *(uint2*)&g_Ssp[(size_t)q * 512 + ch0]       = h2;
    *(uint2*)&g_Ssp[(size_t)q * 512 + 256 + ch0] = l2v;
}

// ----------------------------------------------------------------------------
extern "C" void kernel_launch(void* const* d_in, const int* in_sizes, int n_in,
                              void* d_out, int out_size)
{
    const float* query  = (const float*)d_in[0];
    const float* qpos   = (const float*)d_in[1];
    const float* rp     = (const float*)d_in[2];
    const float* W_off  = (const float*)d_in[3];
    const float* b_off  = (const float*)d_in[4];
    const float* W_attn = (const float*)d_in[5];
    const float* b_attn = (const float*)d_in[6];
    const float* W_v    = (const float*)d_in[7];
    const float* b_v    = (const float*)d_in[8];
    const float* W_out  = (const float*)d_in[9];
    const float* b_out  = (const float*)d_in[10];
    float* out = (float*)d_out;

    __nv_bfloat16 *Aq, *Aqc, *Ssp, *Wv, *Woff, *Watt, *Wout;
    float *V, *OFF, *ATT;
    cudaGetSymbolAddress((void**)&Aq,   g_Aq);
    cudaGetSymbolAddress((void**)&Aqc,  g_Aqc);
    cudaGetSymbolAddress((void**)&Ssp,  g_Ssp);
    cudaGetSymbolAddress((void**)&Wv,   g_Wv);
    cudaGetSymbolAddress((void**)&Woff, g_Woff);
    cudaGetSymbolAddress((void**)&Watt, g_Watt);
    cudaGetSymbolAddress((void**)&Wout, g_Wout);
    cudaGetSymbolAddress((void**)&V,    g_V);
    cudaGetSymbolAddress((void**)&OFF,  g_OFF);
    cudaGetSymbolAddress((void**)&ATT,  g_ATT);

    const int MB = (NQ + 127) / 128;  // 176
    dim3 blk(256);

    split_w   <<<224, blk>>>(W_v, W_off, W_attn, W_out);
    split_qcat<<<NQ * 64 / 256, blk>>>(query, qpos);

    // value = q @ W_v + b_v
    mma_gemm<false><<<dim3(MB, 4), blk>>>(Aq, Wv, b_v, nullptr, V, NQ, 256, 512);
    // offsets
    mma_gemm<false><<<dim3(MB, 2), blk>>>(Aqc, Woff, b_off, nullptr, OFF, NQ, 128, 1024);
    // attention logits
    mma_gemm<false><<<dim3(MB, 1), blk>>>(Aqc, Watt, b_attn, nullptr, ATT, NQ, 64, 1024);
    // sampling (writes split S)
    sample_kernel<<<NQ / 4, blk>>>(V, OFF, ATT, rp);
    // out = S @ W_out + b_out + query
    mma_gemm<true><<<dim3(MB, 4), blk>>>(Ssp, Wout, b_out, query, out, NQ, 256, 512);
}

// round 5
// speedup vs baseline: 3.0241x; 1.0392x over previous
#include <cuda_runtime.h>
#include <cuda_fp16.h>
#include <math.h>
#include <stdint.h>

#define NQ     22500
#define GRID_H 150
#define GRID_W 150

// ---------------- scratch (no allocations allowed) ----------------
// Aqc columns: [hi(q) 0..255 | hi(q+p) 256..511 | lo(q) 512..767 | (unused) 768..1023]
__device__ __half g_Aqc [NQ * 1024];
__device__ __half g_Ssp [NQ * 512];     // [hi(S) | lo(S)]
__device__ float  g_V   [NQ * 256];     // value fp32 (sampler input)
__device__ float  g_OFF [NQ * 128];
__device__ float  g_ATT [NQ * 64];
__device__ __half g_Wv  [256 * 256];    // fp16(W) only (residual handled on A side)
__device__ __half g_Wcat[512 * 192];    // [W_off | W_attn] fp16
__device__ __half g_Wout[256 * 256];

// ---------------- helpers ----------------
__device__ __forceinline__ uint32_t smem_u32(const void* p) {
    return (uint32_t)__cvta_generic_to_shared(p);
}
__device__ __forceinline__ void ldsm_x4(uint32_t* r, uint32_t addr) {
    asm volatile("ldmatrix.sync.aligned.m8n8.x4.shared.b16 {%0,%1,%2,%3}, [%4];"
                 : "=r"(r[0]), "=r"(r[1]), "=r"(r[2]), "=r"(r[3]) : "r"(addr));
}
__device__ __forceinline__ void ldsm_x4_t(uint32_t* r, uint32_t addr) {
    asm volatile("ldmatrix.sync.aligned.m8n8.x4.trans.shared.b16 {%0,%1,%2,%3}, [%4];"
                 : "=r"(r[0]), "=r"(r[1]), "=r"(r[2]), "=r"(r[3]) : "r"(addr));
}
__device__ __forceinline__ void mma_f16(float* c, const uint32_t* a, const uint32_t* b) {
    asm volatile(
        "mma.sync.aligned.m16n8k16.row.col.f32.f16.f16.f32 "
        "{%0,%1,%2,%3}, {%4,%5,%6,%7}, {%8,%9}, {%0,%1,%2,%3};"
        : "+f"(c[0]), "+f"(c[1]), "+f"(c[2]), "+f"(c[3])
        : "r"(a[0]), "r"(a[1]), "r"(a[2]), "r"(a[3]), "r"(b[0]), "r"(b[1]));
}
__device__ __forceinline__ void cp16(void* smem, const void* gmem, bool pred) {
    int sz = pred ? 16 : 0;
    asm volatile("cp.async.cg.shared.global [%0], [%1], 16, %2;"
                 :: "r"(smem_u32(smem)), "l"(gmem), "r"(sz) : "memory");
}
__device__ __forceinline__ void cp_commit() {
    asm volatile("cp.async.commit_group;" ::: "memory");
}
template<int N> __device__ __forceinline__ void cp_wait() {
    asm volatile("cp.async.wait_group %0;" :: "n"(N) : "memory");
}

__device__ __forceinline__ uint2 hi4h(float4 v) {
    __half2 h0 = __floats2half2_rn(v.x, v.y);
    __half2 h1 = __floats2half2_rn(v.z, v.w);
    uint2 r; r.x = *(uint32_t*)&h0; r.y = *(uint32_t*)&h1; return r;
}
__device__ __forceinline__ void split4h(float4 v, uint2& h, uint2& l) {
    __half2 h0 = __floats2half2_rn(v.x, v.y);
    __half2 h1 = __floats2half2_rn(v.z, v.w);
    float2 g0 = __half22float2(h0), g1 = __half22float2(h1);
    __half2 l0 = __floats2half2_rn(v.x - g0.x, v.y - g0.y);
    __half2 l1 = __floats2half2_rn(v.z - g1.x, v.w - g1.y);
    h.x = *(uint32_t*)&h0; h.y = *(uint32_t*)&h1;
    l.x = *(uint32_t*)&l0; l.y = *(uint32_t*)&l1;
}

// ---------------- split kernels ----------------
__global__ void __launch_bounds__(256) split_qcat(const float* __restrict__ q,
                                                  const float* __restrict__ qp) {
    int idx = blockIdx.x * 256 + threadIdx.x;       // NQ*64 threads
    int m = idx >> 6;
    int c = (idx & 63) * 4;
    float4 qv = *(const float4*)(q  + (size_t)m * 256 + c);
    float4 pv = *(const float4*)(qp + (size_t)m * 256 + c);
    float4 sv = make_float4(qv.x + pv.x, qv.y + pv.y, qv.z + pv.z, qv.w + pv.w);
    uint2 qh, ql;
    split4h(qv, qh, ql);
    uint2 sh = hi4h(sv);
    *(uint2*)&g_Aqc[(size_t)m * 1024 + c]       = qh;   // hi(q)
    *(uint2*)&g_Aqc[(size_t)m * 1024 + 256 + c] = sh;   // hi(q+p)
    *(uint2*)&g_Aqc[(size_t)m * 1024 + 512 + c] = ql;   // lo(q)
}

__global__ void __launch_bounds__(256) split_w(const float* __restrict__ Wv,
                                               const float* __restrict__ Woff,
                                               const float* __restrict__ Watt,
                                               const float* __restrict__ Wout) {
    int idx = blockIdx.x * 256 + threadIdx.x;   // 57344 float4 slots
    const float* src; __half* dst; int N, ldd, coff, e;
    if      (idx < 16384) { src = Wv;   dst = g_Wv;   N = 256; ldd = 256; coff = 0;   e = idx;         }
    else if (idx < 32768) { src = Woff; dst = g_Wcat; N = 128; ldd = 192; coff = 0;   e = idx - 16384; }
    else if (idx < 40960) { src = Watt; dst = g_Wcat; N = 64;  ldd = 192; coff = 128; e = idx - 32768; }
    else                  { src = Wout; dst = g_Wout; N = 256; ldd = 256; coff = 0;   e = idx - 40960; }
    int n4 = N / 4;
    int k = e / n4;
    int n = (e % n4) * 4;
    float4 v = *(const float4*)(src + (size_t)k * N + n);
    *(uint2*)&dst[(size_t)k * ldd + coff + n] = hi4h(v);
}

// ----------------------------------------------------------------------------
// fp16 tensor-core GEMM. A is pre-split (fp32 accuracy via [hi|lo] columns);
// W rows are read modulo `wrap`+1, so lo(A) columns re-pair with hi(W):
// result = (Ah + Al) * fp16(W)  — only missing term is A*(W - fp16(W)).
// BM=128, BN=64, BK=32. 3-stage cp.async ring, one __syncthreads per slab.
// A smem rows padded to 80B (stride-5x16B => conflict-free ldmatrix without XOR).
// EPI: 0 = value (fp32 out), 1 = fused OFF|ATT (two dests), 2 = out (+identity)
// ----------------------------------------------------------------------------
template<int EPI>
__global__ void __launch_bounds__(256) mma_gemm(
    const __half* __restrict__ A, int lda, int a_gap,
    const __half* __restrict__ B, int ldb, int wrap,
    const float* __restrict__ bias, const float* __restrict__ bias2,
    const float* __restrict__ ident,
    float* __restrict__ C, float* __restrict__ C2,
    int M, int K2)
{
    __shared__ __align__(128) char smem[3 * 14336];  // per stage: A 10240B + B 4096B

    const int tid  = threadIdx.x;
    const int lane = tid & 31;
    const int warp = tid >> 5;
    const int warp_m = warp & 3;
    const int warp_n = warp >> 2;
    const int m0 = blockIdx.x * 128;
    const int n0 = blockIdx.y * 64;

    float c[2][4][4] = {};

    auto Abase = [&](int s) -> char* { return smem + s * 14336; };
    auto Bbase = [&](int s) -> char* { return smem + s * 14336 + 10240; };

    auto issue = [&](int t, int s) {
        int ac = t * 32;
        if (ac >= 256) ac += a_gap;      // value GEMM: skip over hi(q+p) columns
        char* Ab = Abase(s);
        #pragma unroll
        for (int i = 0; i < 2; i++) {    // A: 128 rows x 4 16B-chunks
            int idx = i * 256 + tid;
            int r = idx >> 2, u = idx & 3;
            int m = m0 + r;
            const void* src = A + (size_t)(m < M ? m : M - 1) * lda + ac + u * 8;
            cp16(Ab + r * 80 + u * 16, src, m < M);
        }
        {                                 // B: 32 rows x 8 chunks (swizzled)
            int r = tid >> 3, u = tid & 7;
            int br = (t * 32 + r) & wrap;
            const void* src = B + (size_t)br * ldb + n0 + u * 8;
            cp16(Bbase(s) + r * 128 + ((u ^ (r & 7)) << 4), src, true);
        }
        cp_commit();
    };

    const int a_r    = (lane & 7) + ((lane >> 3) & 1) * 8;
    const int a_koff = ((lane >> 4) & 1) * 16;
    const int b_r    = (lane & 7) + ((lane >> 3) & 1) * 8;
    const int b_u    = (lane >> 4) & 1;

    const int T = K2 >> 5;
    issue(0, 0);
    issue(1, 1);
    for (int t = 0; t < T; t++) {
        if (t + 1 < T) cp_wait<1>(); else cp_wait<0>();
        __syncthreads();                       // retires all readers of buf (t-1)%3
        if (t + 2 < T) issue(t + 2, (t + 2) % 3);
        const char* Ab = Abase(t % 3);
        const char* Bb = Bbase(t % 3);
        #pragma unroll
        for (int k16 = 0; k16 < 2; k16++) {
            uint32_t a[2][4];
            #pragma unroll
            for (int mt = 0; mt < 2; mt++) {
                int r = warp_m * 32 + mt * 16 + a_r;
                ldsm_x4(a[mt], smem_u32(Ab + r * 80 + k16 * 32 + a_koff));
            }
            uint32_t b[4][2];
            #pragma unroll
            for (int ntp = 0; ntp < 2; ntp++) {
                int kr = k16 * 16 + b_r;
                int u  = warp_n * 4 + ntp * 2 + b_u;
                uint32_t rr[4];
                ldsm_x4_t(rr, smem_u32(Bb + kr * 128 + ((u ^ (kr & 7)) << 4)));
                b[ntp * 2][0] = rr[0];     b[ntp * 2][1] = rr[1];
                b[ntp * 2 + 1][0] = rr[2]; b[ntp * 2 + 1][1] = rr[3];
            }
            #pragma unroll
            for (int nt = 0; nt < 4; nt++)
                #pragma unroll
                for (int mt = 0; mt < 2; mt++)
                    mma_f16(c[mt][nt], a[mt], b[nt]);
        }
    }

    // ---- epilogue ----
    const int gid = lane >> 2, tig = lane & 3;
    float*       dst  = C;
    const float* bs   = bias;
    int          ldc  = ldb;
    int          cbase = n0;
    if (EPI == 1) {
        bool is_att = (n0 >= 128);
        dst   = is_att ? C2 : C;
        bs    = is_att ? bias2 : bias;
        ldc   = is_att ? 64 : 128;
        cbase = is_att ? n0 - 128 : n0;
    }
    #pragma unroll
    for (int mt = 0; mt < 2; mt++) {
        #pragma unroll
        for (int nt = 0; nt < 4; nt++) {
            int cc = cbase + warp_n * 32 + nt * 8 + tig * 2;
            float b0 = bs[cc], b1 = bs[cc + 1];
            int r0 = m0 + warp_m * 32 + mt * 16 + gid;
            if (r0 < M) {
                float2 o = make_float2(c[mt][nt][0] + b0, c[mt][nt][1] + b1);
                if (EPI == 2) {
                    float2 id = *(const float2*)(ident + (size_t)r0 * ldc + cc);
                    o.x += id.x; o.y += id.y;
                }
                *(float2*)(dst + (size_t)r0 * ldc + cc) = o;
            }
            int r1 = r0 + 8;
            if (r1 < M) {
                float2 o = make_float2(c[mt][nt][2] + b0, c[mt][nt][3] + b1);
                if (EPI == 2) {
                    float2 id = *(const float2*)(ident + (size_t)r1 * ldc + cc);
                    o.x += id.x; o.y += id.y;
                }
                *(float2*)(dst + (size_t)r1 * ldc + cc) = o;
            }
        }
    }
}

// ----------------------------------------------------------------------------
// Deformable sampling: 32 threads/query (8 heads x 4 groups), 8 channels/thread.
// Writes S pre-split (fp16 hi|lo) for the output GEMM.
// ----------------------------------------------------------------------------
__global__ void __launch_bounds__(256) sample_kernel(
    const float* __restrict__ V, const float* __restrict__ OFF,
    const float* __restrict__ ATT, const float* __restrict__ RP)
{
    const int q = blockIdx.x * 8 + (threadIdx.x >> 5);
    if (q >= NQ) return;
    const int lane = threadIdx.x & 31;
    const int h    = lane >> 2;
    const int ch0  = h * 32 + (lane & 3) * 8;

    const float* att = ATT + (size_t)q * 64 + h * 8;
    const float* off = OFF + (size_t)q * 128 + h * 16;

    float4 acc0 = make_float4(0.f, 0.f, 0.f, 0.f);
    float4 acc1 = make_float4(0.f, 0.f, 0.f, 0.f);
    #pragma unroll
    for (int qu = 0; qu < 2; qu++) {
        float l0 = att[qu * 4 + 0], l1 = att[qu * 4 + 1];
        float l2 = att[qu * 4 + 2], l3 = att[qu * 4 + 3];
        float mx = fmaxf(fmaxf(l0, l1), fmaxf(l2, l3));
        float e0 = __expf(l0 - mx), e1 = __expf(l1 - mx);
        float e2 = __expf(l2 - mx), e3 = __expf(l3 - mx);
        float inv = 1.f / (e0 + e1 + e2 + e3);
        float w[4] = {e0 * inv, e1 * inv, e2 * inv, e3 * inv};

        float rpx = RP[(size_t)qu * NQ * 2 + (size_t)q * 2 + 0];
        float rpy = RP[(size_t)qu * NQ * 2 + (size_t)q * 2 + 1];

        #pragma unroll
        for (int p = 0; p < 4; p++) {
            float ox = off[qu * 8 + p * 2 + 0];
            float oy = off[qu * 8 + p * 2 + 1];
            float x = (rpx + ox * (1.f / GRID_W)) * GRID_W - 0.5f;
            float y = (rpy + oy * (1.f / GRID_H)) * GRID_H - 0.5f;
            float x0f = floorf(x), y0f = floorf(y);
            float wx = x - x0f, wy = y - y0f;
            int x0 = (int)x0f, y0 = (int)y0f;
            float aw = w[p];
            float tw[4] = {aw * (1.f - wx) * (1.f - wy), aw * wx * (1.f - wy),
                           aw * (1.f - wx) * wy,          aw * wx * wy};
            int xs[4] = {x0, x0 + 1, x0,     x0 + 1};
            int ys[4] = {y0, y0,     y0 + 1, y0 + 1};
            #pragma unroll
            for (int t = 0; t < 4; t++) {
                int xx = xs[t], yy = ys[t];
                if (xx >= 0 && xx < GRID_W && yy >= 0 && yy < GRID_H) {
                    const float* vp = V + ((size_t)yy * GRID_W + xx) * 256 + ch0;
                    float4 v0 = __ldg((const float4*)vp);
                    float4 v1 = __ldg((const float4*)(vp + 4));
                    float wt = tw[t];
                    acc0.x += v0.x * wt; acc0.y += v0.y * wt;
                    acc0.z += v0.z * wt; acc0.w += v0.w * wt;
                    acc1.x += v1.x * wt; acc1.y += v1.y * wt;
                    acc1.z += v1.z * wt; acc1.w += v1.w * wt;
                }
            }
        }
    }
    acc0.x *= 0.5f; acc0.y *= 0.5f; acc0.z *= 0.5f; acc0.w *= 0.5f;
    acc1.x *= 0.5f; acc1.y *= 0.5f; acc1.z *= 0.5f; acc1.w *= 0.5f;
    uint2 h0, l0v, h1, l1v;
    split4h(acc0, h0, l0v);
    split4h(acc1, h1, l1v);
    __half* Sq = g_Ssp + (size_t)q * 512;
    *(uint2*)&Sq[ch0]           = h0;
    *(uint2*)&Sq[ch0 + 4]       = h1;
    *(uint2*)&Sq[256 + ch0]     = l0v;
    *(uint2*)&Sq[256 + ch0 + 4] = l1v;
}

// ----------------------------------------------------------------------------
extern "C" void kernel_launch(void* const* d_in, const int* in_sizes, int n_in,
                              void* d_out, int out_size)
{
    const float* query  = (const float*)d_in[0];
    const float* qpos   = (const float*)d_in[1];
    const float* rp     = (const float*)d_in[2];
    const float* W_off  = (const float*)d_in[3];
    const float* b_off  = (const float*)d_in[4];
    const float* W_attn = (const float*)d_in[5];
    const float* b_attn = (const float*)d_in[6];
    const float* W_v    = (const float*)d_in[7];
    const float* b_v    = (const float*)d_in[8];
    const float* W_out  = (const float*)d_in[9];
    const float* b_out  = (const float*)d_in[10];
    float* out = (float*)d_out;

    __half *Aqc, *Ssp, *Wv, *Wcat, *Wout;
    float *V, *OFF, *ATT;
    cudaGetSymbolAddress((void**)&Aqc,  g_Aqc);
    cudaGetSymbolAddress((void**)&Ssp,  g_Ssp);
    cudaGetSymbolAddress((void**)&Wv,   g_Wv);
    cudaGetSymbolAddress((void**)&Wcat, g_Wcat);
    cudaGetSymbolAddress((void**)&Wout, g_Wout);
    cudaGetSymbolAddress((void**)&V,    g_V);
    cudaGetSymbolAddress((void**)&OFF,  g_OFF);
    cudaGetSymbolAddress((void**)&ATT,  g_ATT);

    const int MB = (NQ + 127) / 128;  // 176
    dim3 blk(256);

    split_w   <<<224, blk>>>(W_v, W_off, W_attn, W_out);
    split_qcat<<<NQ * 64 / 256, blk>>>(query, qpos);

    // value = q @ W_v + b_v   (A = [hi(q)|lo(q)] via a_gap; W wraps mod 256)
    mma_gemm<0><<<dim3(MB, 4), blk>>>(Aqc, 1024, 256, Wv, 256, 255,
                                      b_v, nullptr, nullptr, V, nullptr,
                                      NQ, 512);
    // [offsets | attn] = [hi(q)|hi(q+p)] @ [W_off|W_attn]  (1-term: error-tolerant)
    mma_gemm<1><<<dim3(MB, 3), blk>>>(Aqc, 1024, 0, Wcat, 192, 511,
                                      b_off, b_attn, nullptr, OFF, ATT,
                                      NQ, 512);
    // sampling -> split S
    sample_kernel<<<(NQ + 7) / 8, blk>>>(V, OFF, ATT, rp);
    // out = S @ W_out + b_out + query  (A = [hi(S)|lo(S)]; W wraps mod 256)
    mma_gemm<2><<<dim3(MB, 4), blk>>>(Ssp, 512, 0, Wout, 256, 255,
                                      b_out, nullptr, query, out, nullptr,
                                      NQ, 512);
}

// round 6
// speedup vs baseline: 3.4197x; 1.1308x over previous
#include <cuda_runtime.h>
#include <cuda_fp16.h>
#include <math.h>
#include <stdint.h>

#define NQ     22500
#define GRID_H 150
#define GRID_W 150

// ---------------- scratch (no allocations allowed) ----------------
// Aqc columns: [hi(q) 0..255 | hi(q+p) 256..511 | lo(q) 512..767 | unused]
__device__ __half g_Aqc [NQ * 1024];
__device__ __half g_Ssp [NQ * 512];     // [hi(S) | lo(S)]
__device__ float  g_V   [NQ * 256];
__device__ float  g_OFF [NQ * 128];
__device__ float  g_ATT [NQ * 64];
__device__ __half g_Wv  [256 * 256];
__device__ __half g_Wcat[512 * 192];    // [W_off | W_attn]
__device__ __half g_Wout[256 * 256];

// ---------------- helpers ----------------
__device__ __forceinline__ uint32_t smem_u32(const void* p) {
    return (uint32_t)__cvta_generic_to_shared(p);
}
__device__ __forceinline__ void ldsm_x4(uint32_t* r, uint32_t addr) {
    asm volatile("ldmatrix.sync.aligned.m8n8.x4.shared.b16 {%0,%1,%2,%3}, [%4];"
                 : "=r"(r[0]), "=r"(r[1]), "=r"(r[2]), "=r"(r[3]) : "r"(addr));
}
__device__ __forceinline__ void ldsm_x4_t(uint32_t* r, uint32_t addr) {
    asm volatile("ldmatrix.sync.aligned.m8n8.x4.trans.shared.b16 {%0,%1,%2,%3}, [%4];"
                 : "=r"(r[0]), "=r"(r[1]), "=r"(r[2]), "=r"(r[3]) : "r"(addr));
}
__device__ __forceinline__ void mma_f16(float* c, const uint32_t* a, const uint32_t* b) {
    asm volatile(
        "mma.sync.aligned.m16n8k16.row.col.f32.f16.f16.f32 "
        "{%0,%1,%2,%3}, {%4,%5,%6,%7}, {%8,%9}, {%0,%1,%2,%3};"
        : "+f"(c[0]), "+f"(c[1]), "+f"(c[2]), "+f"(c[3])
        : "r"(a[0]), "r"(a[1]), "r"(a[2]), "r"(a[3]), "r"(b[0]), "r"(b[1]));
}
__device__ __forceinline__ void cp16(void* smem, const void* gmem, bool pred) {
    int sz = pred ? 16 : 0;
    asm volatile("cp.async.cg.shared.global [%0], [%1], 16, %2;"
                 :: "r"(smem_u32(smem)), "l"(gmem), "r"(sz) : "memory");
}
__device__ __forceinline__ void cp_commit() {
    asm volatile("cp.async.commit_group;" ::: "memory");
}
template<int N> __device__ __forceinline__ void cp_wait() {
    asm volatile("cp.async.wait_group %0;" :: "n"(N) : "memory");
}
__device__ __forceinline__ uint2 hi4h(float4 v) {
    __half2 h0 = __floats2half2_rn(v.x, v.y);
    __half2 h1 = __floats2half2_rn(v.z, v.w);
    uint2 r; r.x = *(uint32_t*)&h0; r.y = *(uint32_t*)&h1; return r;
}
__device__ __forceinline__ void split4h(float4 v, uint2& h, uint2& l) {
    __half2 h0 = __floats2half2_rn(v.x, v.y);
    __half2 h1 = __floats2half2_rn(v.z, v.w);
    float2 g0 = __half22float2(h0), g1 = __half22float2(h1);
    __half2 l0 = __floats2half2_rn(v.x - g0.x, v.y - g0.y);
    __half2 l1 = __floats2half2_rn(v.z - g1.x, v.w - g1.y);
    h.x = *(uint32_t*)&h0; h.y = *(uint32_t*)&h1;
    l.x = *(uint32_t*)&l0; l.y = *(uint32_t*)&l1;
}

// ---------------- merged split kernel ----------------
// blocks [0,224): weight conversion; blocks [224, 224+5625): qcat split
__global__ void __launch_bounds__(256) split_all(
    const float* __restrict__ q,   const float* __restrict__ qp,
    const float* __restrict__ Wv,  const float* __restrict__ Woff,
    const float* __restrict__ Watt,const float* __restrict__ Wout)
{
    int b = blockIdx.x;
    if (b < 224) {
        int idx = b * 256 + threadIdx.x;   // 57344 float4 slots
        const float* src; __half* dst; int N, ldd, coff, e;
        if      (idx < 16384) { src = Wv;   dst = g_Wv;   N = 256; ldd = 256; coff = 0;   e = idx;         }
        else if (idx < 32768) { src = Woff; dst = g_Wcat; N = 128; ldd = 192; coff = 0;   e = idx - 16384; }
        else if (idx < 40960) { src = Watt; dst = g_Wcat; N = 64;  ldd = 192; coff = 128; e = idx - 32768; }
        else                  { src = Wout; dst = g_Wout; N = 256; ldd = 256; coff = 0;   e = idx - 40960; }
        int n4 = N / 4;
        int k = e / n4;
        int n = (e % n4) * 4;
        float4 v = *(const float4*)(src + (size_t)k * N + n);
        *(uint2*)&dst[(size_t)k * ldd + coff + n] = hi4h(v);
    } else {
        int idx = (b - 224) * 256 + threadIdx.x;   // NQ*64
        int m = idx >> 6;
        int c = (idx & 63) * 4;
        float4 qv = *(const float4*)(q  + (size_t)m * 256 + c);
        float4 pv = *(const float4*)(qp + (size_t)m * 256 + c);
        float4 sv = make_float4(qv.x + pv.x, qv.y + pv.y, qv.z + pv.z, qv.w + pv.w);
        uint2 qh, ql;
        split4h(qv, qh, ql);
        uint2 sh = hi4h(sv);
        *(uint2*)&g_Aqc[(size_t)m * 1024 + c]       = qh;
        *(uint2*)&g_Aqc[(size_t)m * 1024 + 256 + c] = sh;
        *(uint2*)&g_Aqc[(size_t)m * 1024 + 512 + c] = ql;
    }
}

// ----------------------------------------------------------------------------
// fp16 MMA GEMM, BK=64, 3-stage cp.async ring (dynamic smem 72KB),
// one __syncthreads per 64-K slab (8 total). 128B swizzled rows for A and B.
// MODE 0: fused launch — grid.y 0..3 = value GEMM, 4..6 = [off|attn] GEMM.
// MODE 1: output GEMM (+bias +identity).
// ----------------------------------------------------------------------------
#define STAGE_BYTES 24576   // A 16KB + B 8KB
template<int MODE>
__global__ void __launch_bounds__(256) mma_gemm(
    const __half* __restrict__ A, int lda,
    const __half* __restrict__ B0, const __half* __restrict__ B1,
    const float* __restrict__ bias0, const float* __restrict__ bias1,
    const float* __restrict__ bias2, const float* __restrict__ ident,
    float* __restrict__ D0, float* __restrict__ D1, float* __restrict__ D2,
    int M)
{
    extern __shared__ __align__(128) char smem[];

    const int tid  = threadIdx.x;
    const int lane = tid & 31;
    const int warp = tid >> 5;
    const int warp_m = warp & 3;
    const int warp_n = warp >> 2;
    const int m0 = blockIdx.x * 128;

    // per-block uniform config
    const __half* Bp; int ldb, wrap, n0; bool agap;
    float* dst; const float* bs; int ldc, cbase;
    if (MODE == 0) {
        int y = blockIdx.y;
        if (y < 4) {
            n0 = y * 64; Bp = B0; ldb = 256; wrap = 255; agap = true;
            dst = D0; bs = bias0; ldc = 256; cbase = n0;
        } else {
            n0 = (y - 4) * 64; Bp = B1; ldb = 192; wrap = 511; agap = false;
            if (y < 6) { dst = D1; bs = bias1; ldc = 128; cbase = n0; }
            else       { dst = D2; bs = bias2; ldc = 64;  cbase = 0;  }
        }
    } else {
        n0 = blockIdx.y * 64; Bp = B0; ldb = 256; wrap = 255; agap = false;
        dst = D0; bs = bias0; ldc = 256; cbase = n0;
    }

    float c[2][4][4] = {};

    auto Abase = [&](int s) -> char* { return smem + s * STAGE_BYTES; };
    auto Bbase = [&](int s) -> char* { return smem + s * STAGE_BYTES + 16384; };

    auto issue = [&](int t, int s) {
        int ac = t * 64;
        if (agap && ac >= 256) ac += 256;      // value GEMM: hop to lo(q) columns
        char* Ab = Abase(s);
        #pragma unroll
        for (int i = 0; i < 4; i++) {          // A: 128 rows x 8 16B chunks
            int idx = i * 256 + tid;
            int r = idx >> 3, u = idx & 7;
            int m = m0 + r;
            const void* src = A + (size_t)(m < M ? m : M - 1) * lda + ac + u * 8;
            cp16(Ab + r * 128 + ((u ^ (r & 7)) << 4), src, m < M);
        }
        char* Bb = Bbase(s);
        #pragma unroll
        for (int i = 0; i < 2; i++) {          // B: 64 rows x 8 chunks
            int idx = i * 256 + tid;
            int r = idx >> 3, u = idx & 7;
            int br = (t * 64 + r) & wrap;
            const void* src = Bp + (size_t)br * ldb + n0 + u * 8;
            cp16(Bb + r * 128 + ((u ^ (r & 7)) << 4), src, true);
        }
        cp_commit();
    };

    const int a_r = (lane & 7) + ((lane >> 3) & 1) * 8;
    const int a_u = (lane >> 4) & 1;
    const int b_r = (lane & 7) + ((lane >> 3) & 1) * 8;
    const int b_u = (lane >> 4) & 1;

    const int T = 8;    // K2 = 512 halves for all GEMMs here
    issue(0, 0);
    issue(1, 1);
    for (int t = 0; t < T; t++) {
        if (t + 1 < T) cp_wait<1>(); else cp_wait<0>();
        __syncthreads();                       // retires readers of buf (t-1)%3
        if (t + 2 < T) issue(t + 2, (t + 2) % 3);
        const char* Ab = Abase(t % 3);
        const char* Bb = Bbase(t % 3);
        #pragma unroll
        for (int k16 = 0; k16 < 4; k16++) {
            uint32_t a[2][4];
            #pragma unroll
            for (int mt = 0; mt < 2; mt++) {
                int r = warp_m * 32 + mt * 16 + a_r;
                int u = k16 * 2 + a_u;
                ldsm_x4(a[mt], smem_u32(Ab + r * 128 + ((u ^ (r & 7)) << 4)));
            }
            uint32_t b[4][2];
            #pragma unroll
            for (int ntp = 0; ntp < 2; ntp++) {
                int kr = k16 * 16 + b_r;
                int u  = warp_n * 4 + ntp * 2 + b_u;
                uint32_t rr[4];
                ldsm_x4_t(rr, smem_u32(Bb + kr * 128 + ((u ^ (kr & 7)) << 4)));
                b[ntp * 2][0] = rr[0];     b[ntp * 2][1] = rr[1];
                b[ntp * 2 + 1][0] = rr[2]; b[ntp * 2 + 1][1] = rr[3];
            }
            #pragma unroll
            for (int nt = 0; nt < 4; nt++)
                #pragma unroll
                for (int mt = 0; mt < 2; mt++)
                    mma_f16(c[mt][nt], a[mt], b[nt]);
        }
    }

    // ---- epilogue ----
    const int gid = lane >> 2, tig = lane & 3;
    #pragma unroll
    for (int mt = 0; mt < 2; mt++) {
        #pragma unroll
        for (int nt = 0; nt < 4; nt++) {
            int cc = cbase + warp_n * 32 + nt * 8 + tig * 2;
            float b0 = bs[cc], b1 = bs[cc + 1];
            int r0 = m0 + warp_m * 32 + mt * 16 + gid;
            if (r0 < M) {
                float2 o = make_float2(c[mt][nt][0] + b0, c[mt][nt][1] + b1);
                if (MODE == 1) {
                    float2 id = *(const float2*)(ident + (size_t)r0 * ldc + cc);
                    o.x += id.x; o.y += id.y;
                }
                *(float2*)(dst + (size_t)r0 * ldc + cc) = o;
            }
            int r1 = r0 + 8;
            if (r1 < M) {
                float2 o = make_float2(c[mt][nt][2] + b0, c[mt][nt][3] + b1);
                if (MODE == 1) {
                    float2 id = *(const float2*)(ident + (size_t)r1 * ldc + cc);
                    o.x += id.x; o.y += id.y;
                }
                *(float2*)(dst + (size_t)r1 * ldc + cc) = o;
            }
        }
    }
}

// ----------------------------------------------------------------------------
// Deformable sampling: 32 threads/query (8 heads x 4 groups), 8 channels/thread.
// Writes S pre-split (fp16 hi|lo) for the output GEMM.
// ----------------------------------------------------------------------------
__global__ void __launch_bounds__(256) sample_kernel(
    const float* __restrict__ V, const float* __restrict__ OFF,
    const float* __restrict__ ATT, const float* __restrict__ RP)
{
    const int q = blockIdx.x * 8 + (threadIdx.x >> 5);
    if (q >= NQ) return;
    const int lane = threadIdx.x & 31;
    const int h    = lane >> 2;
    const int ch0  = h * 32 + (lane & 3) * 8;

    const float* att = ATT + (size_t)q * 64 + h * 8;
    const float* off = OFF + (size_t)q * 128 + h * 16;

    float4 acc0 = make_float4(0.f, 0.f, 0.f, 0.f);
    float4 acc1 = make_float4(0.f, 0.f, 0.f, 0.f);
    #pragma unroll
    for (int qu = 0; qu < 2; qu++) {
        float l0 = att[qu * 4 + 0], l1 = att[qu * 4 + 1];
        float l2 = att[qu * 4 + 2], l3 = att[qu * 4 + 3];
        float mx = fmaxf(fmaxf(l0, l1), fmaxf(l2, l3));
        float e0 = __expf(l0 - mx), e1 = __expf(l1 - mx);
        float e2 = __expf(l2 - mx), e3 = __expf(l3 - mx);
        float inv = 1.f / (e0 + e1 + e2 + e3);
        float w[4] = {e0 * inv, e1 * inv, e2 * inv, e3 * inv};

        float rpx = RP[(size_t)qu * NQ * 2 + (size_t)q * 2 + 0];
        float rpy = RP[(size_t)qu * NQ * 2 + (size_t)q * 2 + 1];

        #pragma unroll
        for (int p = 0; p < 4; p++) {
            float ox = off[qu * 8 + p * 2 + 0];
            float oy = off[qu * 8 + p * 2 + 1];
            float x = (rpx + ox * (1.f / GRID_W)) * GRID_W - 0.5f;
            float y = (rpy + oy * (1.f / GRID_H)) * GRID_H - 0.5f;
            float x0f = floorf(x), y0f = floorf(y);
            float wx = x - x0f, wy = y - y0f;
            int x0 = (int)x0f, y0 = (int)y0f;
            float aw = w[p];
            float tw[4] = {aw * (1.f - wx) * (1.f - wy), aw * wx * (1.f - wy),
                           aw * (1.f - wx) * wy,          aw * wx * wy};
            int xs[4] = {x0, x0 + 1, x0,     x0 + 1};
            int ys[4] = {y0, y0,     y0 + 1, y0 + 1};
            #pragma unroll
            for (int t = 0; t < 4; t++) {
                int xx = xs[t], yy = ys[t];
                if (xx >= 0 && xx < GRID_W && yy >= 0 && yy < GRID_H) {
                    const float* vp = V + ((size_t)yy * GRID_W + xx) * 256 + ch0;
                    float4 v0 = __ldg((const float4*)vp);
                    float4 v1 = __ldg((const float4*)(vp + 4));
                    float wt = tw[t];
                    acc0.x += v0.x * wt; acc0.y += v0.y * wt;
                    acc0.z += v0.z * wt; acc0.w += v0.w * wt;
                    acc1.x += v1.x * wt; acc1.y += v1.y * wt;
                    acc1.z += v1.z * wt; acc1.w += v1.w * wt;
                }
            }
        }
    }
    acc0.x *= 0.5f; acc0.y *= 0.5f; acc0.z *= 0.5f; acc0.w *= 0.5f;
    acc1.x *= 0.5f; acc1.y *= 0.5f; acc1.z *= 0.5f; acc1.w *= 0.5f;
    uint2 h0, l0v, h1, l1v;
    split4h(acc0, h0, l0v);
    split4h(acc1, h1, l1v);
    __half* Sq = g_Ssp + (size_t)q * 512;
    *(uint2*)&Sq[ch0]           = h0;
    *(uint2*)&Sq[ch0 + 4]       = h1;
    *(uint2*)&Sq[256 + ch0]     = l0v;
    *(uint2*)&Sq[256 + ch0 + 4] = l1v;
}

// ----------------------------------------------------------------------------
extern "C" void kernel_launch(void* const* d_in, const int* in_sizes, int n_in,
                              void* d_out, int out_size)
{
    const float* query  = (const float*)d_in[0];
    const float* qpos   = (const float*)d_in[1];
    const float* rp     = (const float*)d_in[2];
    const float* W_off  = (const float*)d_in[3];
    const float* b_off  = (const float*)d_in[4];
    const float* W_attn = (const float*)d_in[5];
    const float* b_attn = (const float*)d_in[6];
    const float* W_v    = (const float*)d_in[7];
    const float* b_v    = (const float*)d_in[8];
    const float* W_out  = (const float*)d_in[9];
    const float* b_out  = (const float*)d_in[10];
    float* out = (float*)d_out;

    __half *Aqc, *Ssp, *Wv, *Wcat, *Wout;
    float *V, *OFF, *ATT;
    cudaGetSymbolAddress((void**)&Aqc,  g_Aqc);
    cudaGetSymbolAddress((void**)&Ssp,  g_Ssp);
    cudaGetSymbolAddress((void**)&Wv,   g_Wv);
    cudaGetSymbolAddress((void**)&Wcat, g_Wcat);
    cudaGetSymbolAddress((void**)&Wout, g_Wout);
    cudaGetSymbolAddress((void**)&V,    g_V);
    cudaGetSymbolAddress((void**)&OFF,  g_OFF);
    cudaGetSymbolAddress((void**)&ATT,  g_ATT);

    const int SMEM = 3 * STAGE_BYTES;   // 73728
    cudaFuncSetAttribute(mma_gemm<0>, cudaFuncAttributeMaxDynamicSharedMemorySize, SMEM);
    cudaFuncSetAttribute(mma_gemm<1>, cudaFuncAttributeMaxDynamicSharedMemorySize, SMEM);

    const int MB = (NQ + 127) / 128;  // 176
    dim3 blk(256);

    // splits (weights + qcat) in one launch
    split_all<<<224 + NQ * 64 / 256, blk>>>(query, qpos, W_v, W_off, W_attn, W_out);

    // fused: value GEMM (y 0..3) + [off|attn] GEMM (y 4..6)
    mma_gemm<0><<<dim3(MB, 7), blk, SMEM>>>(Aqc, 1024, Wv, Wcat,
                                            b_v, b_off, b_attn, nullptr,
                                            V, OFF, ATT, NQ);
    // sampling -> split S
    sample_kernel<<<(NQ + 7) / 8, blk>>>(V, OFF, ATT, rp);

    // out = S @ W_out + b_out + query
    mma_gemm<1><<<dim3(MB, 4), blk, SMEM>>>(Ssp, 512, Wout, nullptr,
                                            b_out, nullptr, nullptr, query,
                                            out, nullptr, nullptr, NQ);
}

// round 7
// speedup vs baseline: 3.8810x; 1.1349x over previous
#include <cuda_runtime.h>
#include <cuda_fp16.h>
#include <math.h>
#include <stdint.h>

#define NQ     22500
#define GRID_H 150
#define GRID_W 150

// ---------------- scratch (no allocations allowed) ----------------
// Aqc columns: [hi(q) 0..255 | hi(q+p) 256..511]
__device__ __half g_Aqc [NQ * 512];
__device__ __half g_S16 [NQ * 256];     // fp16(S)
__device__ float  g_V   [NQ * 256];
__device__ float  g_OFF [NQ * 128];
__device__ float  g_ATT [NQ * 64];
__device__ __half g_Wv  [256 * 256];
__device__ __half g_Wcat[512 * 192];    // [W_off | W_attn]
__device__ __half g_Wout[256 * 256];

// ---------------- helpers ----------------
__device__ __forceinline__ uint32_t smem_u32(const void* p) {
    return (uint32_t)__cvta_generic_to_shared(p);
}
__device__ __forceinline__ void ldsm_x4(uint32_t* r, uint32_t addr) {
    asm volatile("ldmatrix.sync.aligned.m8n8.x4.shared.b16 {%0,%1,%2,%3}, [%4];"
                 : "=r"(r[0]), "=r"(r[1]), "=r"(r[2]), "=r"(r[3]) : "r"(addr));
}
__device__ __forceinline__ void ldsm_x4_t(uint32_t* r, uint32_t addr) {
    asm volatile("ldmatrix.sync.aligned.m8n8.x4.trans.shared.b16 {%0,%1,%2,%3}, [%4];"
                 : "=r"(r[0]), "=r"(r[1]), "=r"(r[2]), "=r"(r[3]) : "r"(addr));
}
__device__ __forceinline__ void mma_f16(float* c, const uint32_t* a, const uint32_t* b) {
    asm volatile(
        "mma.sync.aligned.m16n8k16.row.col.f32.f16.f16.f32 "
        "{%0,%1,%2,%3}, {%4,%5,%6,%7}, {%8,%9}, {%0,%1,%2,%3};"
        : "+f"(c[0]), "+f"(c[1]), "+f"(c[2]), "+f"(c[3])
        : "r"(a[0]), "r"(a[1]), "r"(a[2]), "r"(a[3]), "r"(b[0]), "r"(b[1]));
}
__device__ __forceinline__ void cp16(void* smem, const void* gmem, bool pred) {
    int sz = pred ? 16 : 0;
    asm volatile("cp.async.cg.shared.global [%0], [%1], 16, %2;"
                 :: "r"(smem_u32(smem)), "l"(gmem), "r"(sz) : "memory");
}
__device__ __forceinline__ void cp_commit() {
    asm volatile("cp.async.commit_group;" ::: "memory");
}
template<int N> __device__ __forceinline__ void cp_wait() {
    asm volatile("cp.async.wait_group %0;" :: "n"(N) : "memory");
}
__device__ __forceinline__ uint2 hi4h(float4 v) {
    __half2 h0 = __floats2half2_rn(v.x, v.y);
    __half2 h1 = __floats2half2_rn(v.z, v.w);
    uint2 r; r.x = *(uint32_t*)&h0; r.y = *(uint32_t*)&h1; return r;
}

// ---------------- merged split kernel ----------------
// blocks [0,224): weight conversion; blocks [224, 224+5625): qcat convert
__global__ void __launch_bounds__(256) split_all(
    const float* __restrict__ q,   const float* __restrict__ qp,
    const float* __restrict__ Wv,  const float* __restrict__ Woff,
    const float* __restrict__ Watt,const float* __restrict__ Wout)
{
    int b = blockIdx.x;
    if (b < 224) {
        int idx = b * 256 + threadIdx.x;   // 57344 float4 slots
        const float* src; __half* dst; int N, ldd, coff, e;
        if      (idx < 16384) { src = Wv;   dst = g_Wv;   N = 256; ldd = 256; coff = 0;   e = idx;         }
        else if (idx < 32768) { src = Woff; dst = g_Wcat; N = 128; ldd = 192; coff = 0;   e = idx - 16384; }
        else if (idx < 40960) { src = Watt; dst = g_Wcat; N = 64;  ldd = 192; coff = 128; e = idx - 32768; }
        else                  { src = Wout; dst = g_Wout; N = 256; ldd = 256; coff = 0;   e = idx - 40960; }
        int n4 = N / 4;
        int k = e / n4;
        int n = (e % n4) * 4;
        float4 v = *(const float4*)(src + (size_t)k * N + n);
        *(uint2*)&dst[(size_t)k * ldd + coff + n] = hi4h(v);
    } else {
        int idx = (b - 224) * 256 + threadIdx.x;   // NQ*64
        int m = idx >> 6;
        int c = (idx & 63) * 4;
        float4 qv = *(const float4*)(q  + (size_t)m * 256 + c);
        float4 pv = *(const float4*)(qp + (size_t)m * 256 + c);
        float4 sv = make_float4(qv.x + pv.x, qv.y + pv.y, qv.z + pv.z, qv.w + pv.w);
        *(uint2*)&g_Aqc[(size_t)m * 512 + c]       = hi4h(qv);
        *(uint2*)&g_Aqc[(size_t)m * 512 + 256 + c] = hi4h(sv);
    }
}

// ----------------------------------------------------------------------------
// fp16 MMA GEMM, BK=64, 3-stage cp.async ring (dynamic smem 72KB),
// one __syncthreads per 64-K slab. 128B swizzled rows for A and B.
// MODE 0: fused — grid.y 0..3 = value GEMM (K=256), 4..6 = [off|attn] (K=512).
// MODE 1: output GEMM, K=256 (+bias +identity).
// ----------------------------------------------------------------------------
#define STAGE_BYTES 24576   // A 16KB + B 8KB
template<int MODE>
__global__ void __launch_bounds__(256) mma_gemm(
    const __half* __restrict__ A, int lda,
    const __half* __restrict__ B0, const __half* __restrict__ B1,
    const float* __restrict__ bias0, const float* __restrict__ bias1,
    const float* __restrict__ bias2, const float* __restrict__ ident,
    float* __restrict__ D0, float* __restrict__ D1, float* __restrict__ D2,
    int M)
{
    extern __shared__ __align__(128) char smem[];

    const int tid  = threadIdx.x;
    const int lane = tid & 31;
    const int warp = tid >> 5;
    const int warp_m = warp & 3;
    const int warp_n = warp >> 2;
    const int m0 = blockIdx.x * 128;

    // per-block uniform config
    const __half* Bp; int ldb, n0, T;
    float* dst; const float* bs; int ldc, cbase;
    if (MODE == 0) {
        int y = blockIdx.y;
        if (y < 4) {
            n0 = y * 64; Bp = B0; ldb = 256; T = 4;
            dst = D0; bs = bias0; ldc = 256; cbase = n0;
        } else {
            n0 = (y - 4) * 64; Bp = B1; ldb = 192; T = 8;
            if (y < 6) { dst = D1; bs = bias1; ldc = 128; cbase = n0; }
            else       { dst = D2; bs = bias2; ldc = 64;  cbase = 0;  }
        }
    } else {
        n0 = blockIdx.y * 64; Bp = B0; ldb = 256; T = 4;
        dst = D0; bs = bias0; ldc = 256; cbase = n0;
    }

    float c[2][4][4] = {};

    auto Abase = [&](int s) -> char* { return smem + s * STAGE_BYTES; };
    auto Bbase = [&](int s) -> char* { return smem + s * STAGE_BYTES + 16384; };

    auto issue = [&](int t, int s) {
        int ac = t * 64;
        char* Ab = Abase(s);
        #pragma unroll
        for (int i = 0; i < 4; i++) {          // A: 128 rows x 8 16B chunks
            int idx = i * 256 + tid;
            int r = idx >> 3, u = idx & 7;
            int m = m0 + r;
            const void* src = A + (size_t)(m < M ? m : M - 1) * lda + ac + u * 8;
            cp16(Ab + r * 128 + ((u ^ (r & 7)) << 4), src, m < M);
        }
        char* Bb = Bbase(s);
        #pragma unroll
        for (int i = 0; i < 2; i++) {          // B: 64 rows x 8 chunks
            int idx = i * 256 + tid;
            int r = idx >> 3, u = idx & 7;
            const void* src = Bp + (size_t)(t * 64 + r) * ldb + n0 + u * 8;
            cp16(Bb + r * 128 + ((u ^ (r & 7)) << 4), src, true);
        }
        cp_commit();
    };

    const int a_r = (lane & 7) + ((lane >> 3) & 1) * 8;
    const int a_u = (lane >> 4) & 1;
    const int b_r = (lane & 7) + ((lane >> 3) & 1) * 8;
    const int b_u = (lane >> 4) & 1;

    issue(0, 0);
    issue(1, 1);
    for (int t = 0; t < T; t++) {
        if (t + 1 < T) cp_wait<1>(); else cp_wait<0>();
        __syncthreads();                       // retires readers of buf (t-1)%3
        if (t + 2 < T) issue(t + 2, (t + 2) % 3);
        const char* Ab = Abase(t % 3);
        const char* Bb = Bbase(t % 3);
        #pragma unroll
        for (int k16 = 0; k16 < 4; k16++) {
            uint32_t a[2][4];
            #pragma unroll
            for (int mt = 0; mt < 2; mt++) {
                int r = warp_m * 32 + mt * 16 + a_r;
                int u = k16 * 2 + a_u;
                ldsm_x4(a[mt], smem_u32(Ab + r * 128 + ((u ^ (r & 7)) << 4)));
            }
            uint32_t b[4][2];
            #pragma unroll
            for (int ntp = 0; ntp < 2; ntp++) {
                int kr = k16 * 16 + b_r;
                int u  = warp_n * 4 + ntp * 2 + b_u;
                uint32_t rr[4];
                ldsm_x4_t(rr, smem_u32(Bb + kr * 128 + ((u ^ (kr & 7)) << 4)));
                b[ntp * 2][0] = rr[0];     b[ntp * 2][1] = rr[1];
                b[ntp * 2 + 1][0] = rr[2]; b[ntp * 2 + 1][1] = rr[3];
            }
            #pragma unroll
            for (int nt = 0; nt < 4; nt++)
                #pragma unroll
                for (int mt = 0; mt < 2; mt++)
                    mma_f16(c[mt][nt], a[mt], b[nt]);
        }
    }

    // ---- epilogue ----
    const int gid = lane >> 2, tig = lane & 3;
    #pragma unroll
    for (int mt = 0; mt < 2; mt++) {
        #pragma unroll
        for (int nt = 0; nt < 4; nt++) {
            int cc = cbase + warp_n * 32 + nt * 8 + tig * 2;
            float b0 = bs[cc], b1 = bs[cc + 1];
            int r0 = m0 + warp_m * 32 + mt * 16 + gid;
            if (r0 < M) {
                float2 o = make_float2(c[mt][nt][0] + b0, c[mt][nt][1] + b1);
                if (MODE == 1) {
                    float2 id = *(const float2*)(ident + (size_t)r0 * ldc + cc);
                    o.x += id.x; o.y += id.y;
                }
                *(float2*)(dst + (size_t)r0 * ldc + cc) = o;
            }
            int r1 = r0 + 8;
            if (r1 < M) {
                float2 o = make_float2(c[mt][nt][2] + b0, c[mt][nt][3] + b1);
                if (MODE == 1) {
                    float2 id = *(const float2*)(ident + (size_t)r1 * ldc + cc);
                    o.x += id.x; o.y += id.y;
                }
                *(float2*)(dst + (size_t)r1 * ldc + cc) = o;
            }
        }
    }
}

// ----------------------------------------------------------------------------
// Deformable sampling: 32 threads/query (8 heads x 4 groups), 8 channels/thread.
// Writes fp16 S directly (1-term out-GEMM consumes it).
// ----------------------------------------------------------------------------
__global__ void __launch_bounds__(256) sample_kernel(
    const float* __restrict__ V, const float* __restrict__ OFF,
    const float* __restrict__ ATT, const float* __restrict__ RP)
{
    const int q = blockIdx.x * 8 + (threadIdx.x >> 5);
    if (q >= NQ) return;
    const int lane = threadIdx.x & 31;
    const int h    = lane >> 2;
    const int ch0  = h * 32 + (lane & 3) * 8;

    const float* att = ATT + (size_t)q * 64 + h * 8;
    const float* off = OFF + (size_t)q * 128 + h * 16;

    float4 acc0 = make_float4(0.f, 0.f, 0.f, 0.f);
    float4 acc1 = make_float4(0.f, 0.f, 0.f, 0.f);
    #pragma unroll
    for (int qu = 0; qu < 2; qu++) {
        float l0 = att[qu * 4 + 0], l1 = att[qu * 4 + 1];
        float l2 = att[qu * 4 + 2], l3 = att[qu * 4 + 3];
        float mx = fmaxf(fmaxf(l0, l1), fmaxf(l2, l3));
        float e0 = __expf(l0 - mx), e1 = __expf(l1 - mx);
        float e2 = __expf(l2 - mx), e3 = __expf(l3 - mx);
        float inv = 1.f / (e0 + e1 + e2 + e3);
        float w[4] = {e0 * inv, e1 * inv, e2 * inv, e3 * inv};

        float rpx = RP[(size_t)qu * NQ * 2 + (size_t)q * 2 + 0];
        float rpy = RP[(size_t)qu * NQ * 2 + (size_t)q * 2 + 1];

        #pragma unroll
        for (int p = 0; p < 4; p++) {
            float ox = off[qu * 8 + p * 2 + 0];
            float oy = off[qu * 8 + p * 2 + 1];
            float x = (rpx + ox * (1.f / GRID_W)) * GRID_W - 0.5f;
            float y = (rpy + oy * (1.f / GRID_H)) * GRID_H - 0.5f;
            float x0f = floorf(x), y0f = floorf(y);
            float wx = x - x0f, wy = y - y0f;
            int x0 = (int)x0f, y0 = (int)y0f;
            float aw = w[p];
            float tw[4] = {aw * (1.f - wx) * (1.f - wy), aw * wx * (1.f - wy),
                           aw * (1.f - wx) * wy,          aw * wx * wy};
            int xs[4] = {x0, x0 + 1, x0,     x0 + 1};
            int ys[4] = {y0, y0,     y0 + 1, y0 + 1};
            #pragma unroll
            for (int t = 0; t < 4; t++) {
                int xx = xs[t], yy = ys[t];
                if (xx >= 0 && xx < GRID_W && yy >= 0 && yy < GRID_H) {
                    const float* vp = V + ((size_t)yy * GRID_W + xx) * 256 + ch0;
                    float4 v0 = __ldg((const float4*)vp);
                    float4 v1 = __ldg((const float4*)(vp + 4));
                    float wt = tw[t];
                    acc0.x += v0.x * wt; acc0.y += v0.y * wt;
                    acc0.z += v0.z * wt; acc0.w += v0.w * wt;
                    acc1.x += v1.x * wt; acc1.y += v1.y * wt;
                    acc1.z += v1.z * wt; acc1.w += v1.w * wt;
                }
            }
        }
    }
    acc0.x *= 0.5f; acc0.y *= 0.5f; acc0.z *= 0.5f; acc0.w *= 0.5f;
    acc1.x *= 0.5f; acc1.y *= 0.5f; acc1.z *= 0.5f; acc1.w *= 0.5f;
    __half* Sq = g_S16 + (size_t)q * 256;
    *(uint2*)&Sq[ch0]     = hi4h(acc0);
    *(uint2*)&Sq[ch0 + 4] = hi4h(acc1);
}

// ----------------------------------------------------------------------------
extern "C" void kernel_launch(void* const* d_in, const int* in_sizes, int n_in,
                              void* d_out, int out_size)
{
    const float* query  = (const float*)d_in[0];
    const float* qpos   = (const float*)d_in[1];
    const float* rp     = (const float*)d_in[2];
    const float* W_off  = (const float*)d_in[3];
    const float* b_off  = (const float*)d_in[4];
    const float* W_attn = (const float*)d_in[5];
    const float* b_attn = (const float*)d_in[6];
    const float* W_v    = (const float*)d_in[7];
    const float* b_v    = (const float*)d_in[8];
    const float* W_out  = (const float*)d_in[9];
    const float* b_out  = (const float*)d_in[10];
    float* out = (float*)d_out;

    __half *Aqc, *S16, *Wv, *Wcat, *Wout;
    float *V, *OFF, *ATT;
    cudaGetSymbolAddress((void**)&Aqc,  g_Aqc);
    cudaGetSymbolAddress((void**)&S16,  g_S16);
    cudaGetSymbolAddress((void**)&Wv,   g_Wv);
    cudaGetSymbolAddress((void**)&Wcat, g_Wcat);
    cudaGetSymbolAddress((void**)&Wout, g_Wout);
    cudaGetSymbolAddress((void**)&V,    g_V);
    cudaGetSymbolAddress((void**)&OFF,  g_OFF);
    cudaGetSymbolAddress((void**)&ATT,  g_ATT);

    const int SMEM = 3 * STAGE_BYTES;   // 73728
    cudaFuncSetAttribute(mma_gemm<0>, cudaFuncAttributeMaxDynamicSharedMemorySize, SMEM);
    cudaFuncSetAttribute(mma_gemm<1>, cudaFuncAttributeMaxDynamicSharedMemorySize, SMEM);

    const int MB = (NQ + 127) / 128;  // 176
    dim3 blk(256);

    // splits (weights + qcat) in one launch
    split_all<<<224 + NQ * 64 / 256, blk>>>(query, qpos, W_v, W_off, W_attn, W_out);

    // fused: value GEMM (y 0..3, K=256) + [off|attn] GEMM (y 4..6, K=512)
    mma_gemm<0><<<dim3(MB, 7), blk, SMEM>>>(Aqc, 512, Wv, Wcat,
                                            b_v, b_off, b_attn, nullptr,
                                            V, OFF, ATT, NQ);
    // sampling -> fp16 S
    sample_kernel<<<(NQ + 7) / 8, blk>>>(V, OFF, ATT, rp);

    // out = S @ W_out + b_out + query  (K=256)
    mma_gemm<1><<<dim3(MB, 4), blk, SMEM>>>(S16, 256, Wout, nullptr,
                                            b_out, nullptr, nullptr, query,
                                            out, nullptr, nullptr, NQ);
}

// round 10
// speedup vs baseline: 4.4526x; 1.1473x over previous
#include <cuda_runtime.h>
#include <cuda_fp16.h>
#include <math.h>
#include <stdint.h>

#define NQ     22500
#define GRID_H 150
#define GRID_W 150

// ---------------- scratch (no allocations allowed) ----------------
// Aqc columns: [hi(q) 0..255 | hi(q+p) 256..511]
__device__ __half g_Aqc [NQ * 512];
__device__ __half g_S16 [NQ * 256];     // fp16(S)
__device__ __half g_V16 [NQ * 256];     // fp16 value (sampler input)
__device__ float  g_OFF [NQ * 128];
__device__ float  g_ATT [NQ * 64];
__device__ __half g_Wv  [256 * 256];
__device__ __half g_Wcat[512 * 192];    // [W_off | W_attn]
__device__ __half g_Wout[256 * 256];

// ---------------- helpers ----------------
__device__ __forceinline__ uint32_t smem_u32(const void* p) {
    return (uint32_t)__cvta_generic_to_shared(p);
}
__device__ __forceinline__ void ldsm_x4(uint32_t* r, uint32_t addr) {
    asm volatile("ldmatrix.sync.aligned.m8n8.x4.shared.b16 {%0,%1,%2,%3}, [%4];"
                 : "=r"(r[0]), "=r"(r[1]), "=r"(r[2]), "=r"(r[3]) : "r"(addr));
}
__device__ __forceinline__ void ldsm_x4_t(uint32_t* r, uint32_t addr) {
    asm volatile("ldmatrix.sync.aligned.m8n8.x4.trans.shared.b16 {%0,%1,%2,%3}, [%4];"
                 : "=r"(r[0]), "=r"(r[1]), "=r"(r[2]), "=r"(r[3]) : "r"(addr));
}
__device__ __forceinline__ void mma_f16(float* c, const uint32_t* a, const uint32_t* b) {
    asm volatile(
        "mma.sync.aligned.m16n8k16.row.col.f32.f16.f16.f32 "
        "{%0,%1,%2,%3}, {%4,%5,%6,%7}, {%8,%9}, {%0,%1,%2,%3};"
        : "+f"(c[0]), "+f"(c[1]), "+f"(c[2]), "+f"(c[3])
        : "r"(a[0]), "r"(a[1]), "r"(a[2]), "r"(a[3]), "r"(b[0]), "r"(b[1]));
}
__device__ __forceinline__ void cp16(void* smem, const void* gmem, bool pred) {
    int sz = pred ? 16 : 0;
    asm volatile("cp.async.cg.shared.global [%0], [%1], 16, %2;"
                 :: "r"(smem_u32(smem)), "l"(gmem), "r"(sz) : "memory");
}
__device__ __forceinline__ void cp_commit() {
    asm volatile("cp.async.commit_group;" ::: "memory");
}
template<int N> __device__ __forceinline__ void cp_wait() {
    asm volatile("cp.async.wait_group %0;" :: "n"(N) : "memory");
}
__device__ __forceinline__ uint2 hi4h(float4 v) {
    __half2 h0 = __floats2half2_rn(v.x, v.y);
    __half2 h1 = __floats2half2_rn(v.z, v.w);
    uint2 r; r.x = *(uint32_t*)&h0; r.y = *(uint32_t*)&h1; return r;
}

// ---------------- merged split kernel ----------------
// blocks [0,224): weight conversion; blocks [224, 224+5625): qcat convert
__global__ void __launch_bounds__(256) split_all(
    const float* __restrict__ q,   const float* __restrict__ qp,
    const float* __restrict__ Wv,  const float* __restrict__ Woff,
    const float* __restrict__ Watt,const float* __restrict__ Wout)
{
    int b = blockIdx.x;
    if (b < 224) {
        int idx = b * 256 + threadIdx.x;   // 57344 float4 slots
        const float* src; __half* dst; int N, ldd, coff, e;
        if      (idx < 16384) { src = Wv;   dst = g_Wv;   N = 256; ldd = 256; coff = 0;   e = idx;         }
        else if (idx < 32768) { src = Woff; dst = g_Wcat; N = 128; ldd = 192; coff = 0;   e = idx - 16384; }
        else if (idx < 40960) { src = Watt; dst = g_Wcat; N = 64;  ldd = 192; coff = 128; e = idx - 32768; }
        else                  { src = Wout; dst = g_Wout; N = 256; ldd = 256; coff = 0;   e = idx - 40960; }
        int n4 = N / 4;
        int k = e / n4;
        int n = (e % n4) * 4;
        float4 v = *(const float4*)(src + (size_t)k * N + n);
        *(uint2*)&dst[(size_t)k * ldd + coff + n] = hi4h(v);
    } else {
        int idx = (b - 224) * 256 + threadIdx.x;   // NQ*64
        int m = idx >> 6;
        int c = (idx & 63) * 4;
        float4 qv = *(const float4*)(q  + (size_t)m * 256 + c);
        float4 pv = *(const float4*)(qp + (size_t)m * 256 + c);
        float4 sv = make_float4(qv.x + pv.x, qv.y + pv.y, qv.z + pv.z, qv.w + pv.w);
        *(uint2*)&g_Aqc[(size_t)m * 512 + c]       = hi4h(qv);
        *(uint2*)&g_Aqc[(size_t)m * 512 + 256 + c] = hi4h(sv);
    }
}

// ----------------------------------------------------------------------------
// fp16 MMA GEMM, BK=64, 3-stage cp.async ring (dynamic smem 72KB),
// one __syncthreads per 64-K slab. 128B swizzled rows for A and B.
// MODE 0: fused — y 0..3 = value GEMM (K=256, fp16 out), 4..6 = [off|attn] (K=512).
// MODE 1: output GEMM, K=256 (+bias +identity, fp32 out).
// ----------------------------------------------------------------------------
#define STAGE_BYTES 24576   // A 16KB + B 8KB
template<int MODE>
__global__ void __launch_bounds__(256) mma_gemm(
    const __half* __restrict__ A, int lda,
    const __half* __restrict__ B0, const __half* __restrict__ B1,
    const float* __restrict__ bias0, const float* __restrict__ bias1,
    const float* __restrict__ bias2, const float* __restrict__ ident,
    float* __restrict__ D0, __half* __restrict__ D0h,
    float* __restrict__ D1, float* __restrict__ D2,
    int M)
{
    extern __shared__ __align__(128) char smem[];

    const int tid  = threadIdx.x;
    const int lane = tid & 31;
    const int warp = tid >> 5;
    const int warp_m = warp & 3;
    const int warp_n = warp >> 2;
    const int m0 = blockIdx.x * 128;

    // per-block uniform config
    const __half* Bp; int ldb, n0, T;
    float* dst; const float* bs; int ldc, cbase; bool half_out = false;
    if (MODE == 0) {
        int y = blockIdx.y;
        if (y < 4) {
            n0 = y * 64; Bp = B0; ldb = 256; T = 4;
            dst = D0; bs = bias0; ldc = 256; cbase = n0; half_out = true;
        } else {
            n0 = (y - 4) * 64; Bp = B1; ldb = 192; T = 8;
            if (y < 6) { dst = D1; bs = bias1; ldc = 128; cbase = n0; }
            else       { dst = D2; bs = bias2; ldc = 64;  cbase = 0;  }
        }
    } else {
        n0 = blockIdx.y * 64; Bp = B0; ldb = 256; T = 4;
        dst = D0; bs = bias0; ldc = 256; cbase = n0;
    }

    float c[2][4][4] = {};

    auto Abase = [&](int s) -> char* { return smem + s * STAGE_BYTES; };
    auto Bbase = [&](int s) -> char* { return smem + s * STAGE_BYTES + 16384; };

    auto issue = [&](int t, int s) {
        int ac = t * 64;
        char* Ab = Abase(s);
        #pragma unroll
        for (int i = 0; i < 4; i++) {          // A: 128 rows x 8 16B chunks
            int idx = i * 256 + tid;
            int r = idx >> 3, u = idx & 7;
            int m = m0 + r;
            const void* src = A + (size_t)(m < M ? m : M - 1) * lda + ac + u * 8;
            cp16(Ab + r * 128 + ((u ^ (r & 7)) << 4), src, m < M);
        }
        char* Bb = Bbase(s);
        #pragma unroll
        for (int i = 0; i < 2; i++) {          // B: 64 rows x 8 chunks
            int idx = i * 256 + tid;
            int r = idx >> 3, u = idx & 7;
            const void* src = Bp + (size_t)(t * 64 + r) * ldb + n0 + u * 8;
            cp16(Bb + r * 128 + ((u ^ (r & 7)) << 4), src, true);
        }
        cp_commit();
    };

    const int a_r = (lane & 7) + ((lane >> 3) & 1) * 8;
    const int a_u = (lane >> 4) & 1;
    const int b_r = (lane & 7) + ((lane >> 3) & 1) * 8;
    const int b_u = (lane >> 4) & 1;

    issue(0, 0);
    issue(1, 1);
    for (int t = 0; t < T; t++) {
        if (t + 1 < T) cp_wait<1>(); else cp_wait<0>();
        __syncthreads();                       // retires readers of buf (t-1)%3
        if (t + 2 < T) issue(t + 2, (t + 2) % 3);
        const char* Ab = Abase(t % 3);
        const char* Bb = Bbase(t % 3);
        #pragma unroll
        for (int k16 = 0; k16 < 4; k16++) {
            uint32_t a[2][4];
            #pragma unroll
            for (int mt = 0; mt < 2; mt++) {
                int r = warp_m * 32 + mt * 16 + a_r;
                int u = k16 * 2 + a_u;
                ldsm_x4(a[mt], smem_u32(Ab + r * 128 + ((u ^ (r & 7)) << 4)));
            }
            uint32_t b[4][2];
            #pragma unroll
            for (int ntp = 0; ntp < 2; ntp++) {
                int kr = k16 * 16 + b_r;
                int u  = warp_n * 4 + ntp * 2 + b_u;
                uint32_t rr[4];
                ldsm_x4_t(rr, smem_u32(Bb + kr * 128 + ((u ^ (kr & 7)) << 4)));
                b[ntp * 2][0] = rr[0];     b[ntp * 2][1] = rr[1];
                b[ntp * 2 + 1][0] = rr[2]; b[ntp * 2 + 1][1] = rr[3];
            }
            #pragma unroll
            for (int nt = 0; nt < 4; nt++)
                #pragma unroll
                for (int mt = 0; mt < 2; mt++)
                    mma_f16(c[mt][nt], a[mt], b[nt]);
        }
    }

    // ---- epilogue ----
    const int gid = lane >> 2, tig = lane & 3;
    #pragma unroll
    for (int mt = 0; mt < 2; mt++) {
        #pragma unroll
        for (int nt = 0; nt < 4; nt++) {
            int cc = cbase + warp_n * 32 + nt * 8 + tig * 2;
            float b0 = bs[cc], b1 = bs[cc + 1];
            int r0 = m0 + warp_m * 32 + mt * 16 + gid;
            if (r0 < M) {
                float2 o = make_float2(c[mt][nt][0] + b0, c[mt][nt][1] + b1);
                if (MODE == 1) {
                    float2 id = *(const float2*)(ident + (size_t)r0 * ldc + cc);
                    o.x += id.x; o.y += id.y;
                }
                if (MODE == 0 && half_out) {
                    __half2 oh = __floats2half2_rn(o.x, o.y);
                    *(uint32_t*)(D0h + (size_t)r0 * 256 + cc) = *(uint32_t*)&oh;
                } else {
                    *(float2*)(dst + (size_t)r0 * ldc + cc) = o;
                }
            }
            int r1 = r0 + 8;
            if (r1 < M) {
                float2 o = make_float2(c[mt][nt][2] + b0, c[mt][nt][3] + b1);
                if (MODE == 1) {
                    float2 id = *(const float2*)(ident + (size_t)r1 * ldc + cc);
                    o.x += id.x; o.y += id.y;
                }
                if (MODE == 0 && half_out) {
                    __half2 oh = __floats2half2_rn(o.x, o.y);
                    *(uint32_t*)(D0h + (size_t)r1 * 256 + cc) = *(uint32_t*)&oh;
                } else {
                    *(float2*)(dst + (size_t)r1 * ldc + cc) = o;
                }
            }
        }
    }
}

// ----------------------------------------------------------------------------
// Deformable sampling: 32 threads/query (8 heads x 4 groups), 8 channels/thread.
// V is fp16 (16B per tap per thread, uint4 load); fp32 accumulation; fp16 S out.
// ----------------------------------------------------------------------------
__global__ void __launch_bounds__(256) sample_kernel(
    const __half* __restrict__ V, const float* __restrict__ OFF,
    const float* __restrict__ ATT, const float* __restrict__ RP)
{
    const int q = blockIdx.x * 8 + (threadIdx.x >> 5);
    if (q >= NQ) return;
    const int lane = threadIdx.x & 31;
    const int h    = lane >> 2;
    const int ch0  = h * 32 + (lane & 3) * 8;

    const float* att = ATT + (size_t)q * 64 + h * 8;
    const float* off = OFF + (size_t)q * 128 + h * 16;

    float4 acc0 = make_float4(0.f, 0.f, 0.f, 0.f);
    float4 acc1 = make_float4(0.f, 0.f, 0.f, 0.f);
    #pragma unroll
    for (int qu = 0; qu < 2; qu++) {
        float l0 = att[qu * 4 + 0], l1 = att[qu * 4 + 1];
        float l2 = att[qu * 4 + 2], l3 = att[qu * 4 + 3];
        float mx = fmaxf(fmaxf(l0, l1), fmaxf(l2, l3));
        float e0 = __expf(l0 - mx), e1 = __expf(l1 - mx);
        float e2 = __expf(l2 - mx), e3 = __expf(l3 - mx);
        float inv = 1.f / (e0 + e1 + e2 + e3);
        float w[4] = {e0 * inv, e1 * inv, e2 * inv, e3 * inv};

        float rpx = RP[(size_t)qu * NQ * 2 + (size_t)q * 2 + 0];
        float rpy = RP[(size_t)qu * NQ * 2 + (size_t)q * 2 + 1];

        #pragma unroll
        for (int p = 0; p < 4; p++) {
            float ox = off[qu * 8 + p * 2 + 0];
            float oy = off[qu * 8 + p * 2 + 1];
            float x = (rpx + ox * (1.f / GRID_W)) * GRID_W - 0.5f;
            float y = (rpy + oy * (1.f / GRID_H)) * GRID_H - 0.5f;
            float x0f = floorf(x), y0f = floorf(y);
            float wx = x - x0f, wy = y - y0f;
            int x0 = (int)x0f, y0 = (int)y0f;
            float aw = w[p];
            float tw[4] = {aw * (1.f - wx) * (1.f - wy), aw * wx * (1.f - wy),
                           aw * (1.f - wx) * wy,          aw * wx * wy};
            int xs[4] = {x0, x0 + 1, x0,     x0 + 1};
            int ys[4] = {y0, y0,     y0 + 1, y0 + 1};
            #pragma unroll
            for (int t = 0; t < 4; t++) {
                int xx = xs[t], yy = ys[t];
                if (xx >= 0 && xx < GRID_W && yy >= 0 && yy < GRID_H) {
                    uint4 rv = __ldg((const uint4*)(V +
                        ((size_t)yy * GRID_W + xx) * 256 + ch0));
                    const __half2* hp = (const __half2*)&rv;
                    float2 f0 = __half22float2(hp[0]);
                    float2 f1 = __half22float2(hp[1]);
                    float2 f2 = __half22float2(hp[2]);
                    float2 f3 = __half22float2(hp[3]);
                    float wt = tw[t];
                    acc0.x += f0.x * wt; acc0.y += f0.y * wt;
                    acc0.z += f1.x * wt; acc0.w += f1.y * wt;
                    acc1.x += f2.x * wt; acc1.y += f2.y * wt;
                    acc1.z += f3.x * wt; acc1.w += f3.y * wt;
                }
            }
        }
    }
    acc0.x *= 0.5f; acc0.y *= 0.5f; acc0.z *= 0.5f; acc0.w *= 0.5f;
    acc1.x *= 0.5f; acc1.y *= 0.5f; acc1.z *= 0.5f; acc1.w *= 0.5f;
    __half* Sq = g_S16 + (size_t)q * 256;
    *(uint2*)&Sq[ch0]     = hi4h(acc0);
    *(uint2*)&Sq[ch0 + 4] = hi4h(acc1);
}

// ----------------------------------------------------------------------------
extern "C" void kernel_launch(void* const* d_in, const int* in_sizes, int n_in,
                              void* d_out, int out_size)
{
    const float* query  = (const float*)d_in[0];
    const float* qpos   = (const float*)d_in[1];
    const float* rp     = (const float*)d_in[2];
    const float* W_off  = (const float*)d_in[3];
    const float* b_off  = (const float*)d_in[4];
    const float* W_attn = (const float*)d_in[5];
    const float* b_attn = (const float*)d_in[6];
    const float* W_v    = (const float*)d_in[7];
    const float* b_v    = (const float*)d_in[8];
    const float* W_out  = (const float*)d_in[9];
    const float* b_out  = (const float*)d_in[10];
    float* out = (float*)d_out;

    __half *Aqc, *S16, *V16, *Wv, *Wcat, *Wout;
    float *OFF, *ATT;
    cudaGetSymbolAddress((void**)&Aqc,  g_Aqc);
    cudaGetSymbolAddress((void**)&S16,  g_S16);
    cudaGetSymbolAddress((void**)&V16,  g_V16);
    cudaGetSymbolAddress((void**)&Wv,   g_Wv);
    cudaGetSymbolAddress((void**)&Wcat, g_Wcat);
    cudaGetSymbolAddress((void**)&Wout, g_Wout);
    cudaGetSymbolAddress((void**)&OFF,  g_OFF);
    cudaGetSymbolAddress((void**)&ATT,  g_ATT);

    const int SMEM = 3 * STAGE_BYTES;   // 73728
    cudaFuncSetAttribute(mma_gemm<0>, cudaFuncAttributeMaxDynamicSharedMemorySize, SMEM);
    cudaFuncSetAttribute(mma_gemm<1>, cudaFuncAttributeMaxDynamicSharedMemorySize, SMEM);

    const int MB = (NQ + 127) / 128;  // 176
    dim3 blk(256);

    // splits (weights + qcat) in one launch
    split_all<<<224 + NQ * 64 / 256, blk>>>(query, qpos, W_v, W_off, W_attn, W_out);

    // fused: value GEMM (y 0..3, K=256, fp16 out) + [off|attn] GEMM (y 4..6, K=512)
    mma_gemm<0><<<dim3(MB, 7), blk, SMEM>>>(Aqc, 512, Wv, Wcat,
                                            b_v, b_off, b_attn, nullptr,
                                            nullptr, V16, OFF, ATT, NQ);
    // sampling (fp16 V) -> fp16 S
    sample_kernel<<<(NQ + 7) / 8, blk>>>(V16, OFF, ATT, rp);

    // out = S @ W_out + b_out + query  (K=256)
    mma_gemm<1><<<dim3(MB, 4), blk, SMEM>>>(S16, 256, Wout, nullptr,
                                            b_out, nullptr, nullptr, query,
                                            out, nullptr, nullptr, nullptr, NQ);
}

// round 13
// speedup vs baseline: 4.5659x; 1.0254x over previous
#include <cuda_runtime.h>
#include <cuda_fp16.h>
#include <math.h>
#include <stdint.h>

#define NQ     22500
#define GRID_H 150
#define GRID_W 150

// ---------------- scratch (no allocations allowed) ----------------
// Aqc columns: [hi(q) 0..255 | hi(q+p) 256..511]
__device__ __half g_Aqc [NQ * 512];
__device__ __half g_S16 [NQ * 256];     // fp16(S)
__device__ __half g_V16 [NQ * 256];     // fp16 value (sampler input)
__device__ __half g_OFF [NQ * 128];     // fp16 offsets
__device__ __half g_ATT [NQ * 64];      // fp16 attn logits
__device__ __half g_Wv  [256 * 256];
__device__ __half g_Wcat[512 * 192];    // [W_off | W_attn]
__device__ __half g_Wout[256 * 256];

// ---------------- helpers ----------------
__device__ __forceinline__ uint32_t smem_u32(const void* p) {
    return (uint32_t)__cvta_generic_to_shared(p);
}
__device__ __forceinline__ void ldsm_x4(uint32_t* r, uint32_t addr) {
    asm volatile("ldmatrix.sync.aligned.m8n8.x4.shared.b16 {%0,%1,%2,%3}, [%4];"
                 : "=r"(r[0]), "=r"(r[1]), "=r"(r[2]), "=r"(r[3]) : "r"(addr));
}
__device__ __forceinline__ void ldsm_x4_t(uint32_t* r, uint32_t addr) {
    asm volatile("ldmatrix.sync.aligned.m8n8.x4.trans.shared.b16 {%0,%1,%2,%3}, [%4];"
                 : "=r"(r[0]), "=r"(r[1]), "=r"(r[2]), "=r"(r[3]) : "r"(addr));
}
__device__ __forceinline__ void mma_f16(float* c, const uint32_t* a, const uint32_t* b) {
    asm volatile(
        "mma.sync.aligned.m16n8k16.row.col.f32.f16.f16.f32 "
        "{%0,%1,%2,%3}, {%4,%5,%6,%7}, {%8,%9}, {%0,%1,%2,%3};"
        : "+f"(c[0]), "+f"(c[1]), "+f"(c[2]), "+f"(c[3])
        : "r"(a[0]), "r"(a[1]), "r"(a[2]), "r"(a[3]), "r"(b[0]), "r"(b[1]));
}
__device__ __forceinline__ void cp16(void* smem, const void* gmem, bool pred) {
    int sz = pred ? 16 : 0;
    asm volatile("cp.async.cg.shared.global [%0], [%1], 16, %2;"
                 :: "r"(smem_u32(smem)), "l"(gmem), "r"(sz) : "memory");
}
__device__ __forceinline__ void cp_commit() {
    asm volatile("cp.async.commit_group;" ::: "memory");
}
template<int N> __device__ __forceinline__ void cp_wait() {
    asm volatile("cp.async.wait_group %0;" :: "n"(N) : "memory");
}
__device__ __forceinline__ uint2 hi4h(float4 v) {
    __half2 h0 = __floats2half2_rn(v.x, v.y);
    __half2 h1 = __floats2half2_rn(v.z, v.w);
    uint2 r; r.x = *(uint32_t*)&h0; r.y = *(uint32_t*)&h1; return r;
}

// ---------------- merged split kernel ----------------
// blocks [0,224): weight conversion; blocks [224, 224+5625): qcat convert
__global__ void __launch_bounds__(256) split_all(
    const float* __restrict__ q,   const float* __restrict__ qp,
    const float* __restrict__ Wv,  const float* __restrict__ Woff,
    const float* __restrict__ Watt,const float* __restrict__ Wout)
{
    int b = blockIdx.x;
    if (b < 224) {
        int idx = b * 256 + threadIdx.x;   // 57344 float4 slots
        const float* src; __half* dst; int N, ldd, coff, e;
        if      (idx < 16384) { src = Wv;   dst = g_Wv;   N = 256; ldd = 256; coff = 0;   e = idx;         }
        else if (idx < 32768) { src = Woff; dst = g_Wcat; N = 128; ldd = 192; coff = 0;   e = idx - 16384; }
        else if (idx < 40960) { src = Watt; dst = g_Wcat; N = 64;  ldd = 192; coff = 128; e = idx - 32768; }
        else                  { src = Wout; dst = g_Wout; N = 256; ldd = 256; coff = 0;   e = idx - 40960; }
        int n4 = N / 4;
        int k = e / n4;
        int n = (e % n4) * 4;
        float4 v = *(const float4*)(src + (size_t)k * N + n);
        *(uint2*)&dst[(size_t)k * ldd + coff + n] = hi4h(v);
    } else {
        int idx = (b - 224) * 256 + threadIdx.x;   // NQ*64
        int m = idx >> 6;
        int c = (idx & 63) * 4;
        float4 qv = *(const float4*)(q  + (size_t)m * 256 + c);
        float4 pv = *(const float4*)(qp + (size_t)m * 256 + c);
        float4 sv = make_float4(qv.x + pv.x, qv.y + pv.y, qv.z + pv.z, qv.w + pv.w);
        *(uint2*)&g_Aqc[(size_t)m * 512 + c]       = hi4h(qv);
        *(uint2*)&g_Aqc[(size_t)m * 512 + 256 + c] = hi4h(sv);
    }
}

// ----------------------------------------------------------------------------
// fp16 mma.sync GEMM, BK=64, 3-stage cp.async ring (dynamic smem 72KB),
// one __syncthreads per 64-K slab. 128B swizzled rows for A and B.
// MODE 0: fused — y 0..3 = value (K=256), 4..5 = OFF, 6 = ATT (K=512); fp16 out.
// MODE 1: output GEMM, K=256 (+bias +identity, fp32 out).
// ----------------------------------------------------------------------------
#define STAGE_BYTES 24576   // A 16KB + B 8KB
template<int MODE>
__global__ void __launch_bounds__(256) mma_gemm(
    const __half* __restrict__ A, int lda,
    const __half* __restrict__ B0, const __half* __restrict__ B1,
    const float* __restrict__ bias0, const float* __restrict__ bias1,
    const float* __restrict__ bias2, const float* __restrict__ ident,
    float* __restrict__ D0, __half* __restrict__ H0,
    __half* __restrict__ H1, __half* __restrict__ H2,
    int M)
{
    extern __shared__ __align__(128) char smem[];

    const int tid  = threadIdx.x;
    const int lane = tid & 31;
    const int warp = tid >> 5;
    const int warp_m = warp & 3;
    const int warp_n = warp >> 2;
    const int m0 = blockIdx.x * 128;

    // per-block uniform config
    const __half* Bp; int ldb, n0, T;
    __half* dsth = nullptr; const float* bs; int ldc, cbase;
    if (MODE == 0) {
        int y = blockIdx.y;
        if (y < 4) {
            n0 = y * 64; Bp = B0; ldb = 256; T = 4;
            dsth = H0; bs = bias0; ldc = 256; cbase = n0;
        } else {
            n0 = (y - 4) * 64; Bp = B1; ldb = 192; T = 8;
            if (y < 6) { dsth = H1; bs = bias1; ldc = 128; cbase = n0; }
            else       { dsth = H2; bs = bias2; ldc = 64;  cbase = 0;  }
        }
    } else {
        n0 = blockIdx.y * 64; Bp = B0; ldb = 256; T = 4;
        bs = bias0; ldc = 256; cbase = n0;
    }

    float c[2][4][4] = {};

    auto Abase = [&](int s) -> char* { return smem + s * STAGE_BYTES; };
    auto Bbase = [&](int s) -> char* { return smem + s * STAGE_BYTES + 16384; };

    auto issue = [&](int t, int s) {
        int ac = t * 64;
        char* Ab = Abase(s);
        #pragma unroll
        for (int i = 0; i < 4; i++) {          // A: 128 rows x 8 16B chunks
            int idx = i * 256 + tid;
            int r = idx >> 3, u = idx & 7;
            int m = m0 + r;
            const void* src = A + (size_t)(m < M ? m : M - 1) * lda + ac + u * 8;
            cp16(Ab + r * 128 + ((u ^ (r & 7)) << 4), src, m < M);
        }
        char* Bb = Bbase(s);
        #pragma unroll
        for (int i = 0; i < 2; i++) {          // B: 64 rows x 8 chunks
            int idx = i * 256 + tid;
            int r = idx >> 3, u = idx & 7;
            const void* src = Bp + (size_t)(t * 64 + r) * ldb + n0 + u * 8;
            cp16(Bb + r * 128 + ((u ^ (r & 7)) << 4), src, true);
        }
        cp_commit();
    };

    const int a_r = (lane & 7) + ((lane >> 3) & 1) * 8;
    const int a_u = (lane >> 4) & 1;
    const int b_r = (lane & 7) + ((lane >> 3) & 1) * 8;
    const int b_u = (lane >> 4) & 1;

    issue(0, 0);
    issue(1, 1);
    for (int t = 0; t < T; t++) {
        if (t + 1 < T) cp_wait<1>(); else cp_wait<0>();
        __syncthreads();                       // retires readers of buf (t-1)%3
        if (t + 2 < T) issue(t + 2, (t + 2) % 3);
        const char* Ab = Abase(t % 3);
        const char* Bb = Bbase(t % 3);
        #pragma unroll
        for (int k16 = 0; k16 < 4; k16++) {
            uint32_t a[2][4];
            #pragma unroll
            for (int mt = 0; mt < 2; mt++) {
                int r = warp_m * 32 + mt * 16 + a_r;
                int u = k16 * 2 + a_u;
                ldsm_x4(a[mt], smem_u32(Ab + r * 128 + ((u ^ (r & 7)) << 4)));
            }
            uint32_t b[4][2];
            #pragma unroll
            for (int ntp = 0; ntp < 2; ntp++) {
                int kr = k16 * 16 + b_r;
                int u  = warp_n * 4 + ntp * 2 + b_u;
                uint32_t rr[4];
                ldsm_x4_t(rr, smem_u32(Bb + kr * 128 + ((u ^ (kr & 7)) << 4)));
                b[ntp * 2][0] = rr[0];     b[ntp * 2][1] = rr[1];
                b[ntp * 2 + 1][0] = rr[2]; b[ntp * 2 + 1][1] = rr[3];
            }
            #pragma unroll
            for (int nt = 0; nt < 4; nt++)
                #pragma unroll
                for (int mt = 0; mt < 2; mt++)
                    mma_f16(c[mt][nt], a[mt], b[nt]);
        }
    }

    // ---- epilogue ----
    const int gid = lane >> 2, tig = lane & 3;
    #pragma unroll
    for (int mt = 0; mt < 2; mt++) {
        #pragma unroll
        for (int nt = 0; nt < 4; nt++) {
            int cc = cbase + warp_n * 32 + nt * 8 + tig * 2;
            float b0 = bs[cc], b1 = bs[cc + 1];
            int r0 = m0 + warp_m * 32 + mt * 16 + gid;
            if (r0 < M) {
                float2 o = make_float2(c[mt][nt][0] + b0, c[mt][nt][1] + b1);
                if (MODE == 1) {
                    float2 id = *(const float2*)(ident + (size_t)r0 * ldc + cc);
                    o.x += id.x; o.y += id.y;
                    *(float2*)(D0 + (size_t)r0 * ldc + cc) = o;
                } else {
                    __half2 oh = __floats2half2_rn(o.x, o.y);
                    *(uint32_t*)(dsth + (size_t)r0 * ldc + cc) = *(uint32_t*)&oh;
                }
            }
            int r1 = r0 + 8;
            if (r1 < M) {
                float2 o = make_float2(c[mt][nt][2] + b0, c[mt][nt][3] + b1);
                if (MODE == 1) {
                    float2 id = *(const float2*)(ident + (size_t)r1 * ldc + cc);
                    o.x += id.x; o.y += id.y;
                    *(float2*)(D0 + (size_t)r1 * ldc + cc) = o;
                } else {
                    __half2 oh = __floats2half2_rn(o.x, o.y);
                    *(uint32_t*)(dsth + (size_t)r1 * ldc + cc) = *(uint32_t*)&oh;
                }
            }
        }
    }
}

// ----------------------------------------------------------------------------
// Deformable sampling: 32 threads/query (8 heads x 4 groups), 8 channels/thread.
// All inputs fp16 (V, OFF, ATT); fp32 accumulation; fp16 S out.
// ----------------------------------------------------------------------------
__global__ void __launch_bounds__(256) sample_kernel(
    const __half* __restrict__ V, const __half* __restrict__ OFF,
    const __half* __restrict__ ATT, const float* __restrict__ RP)
{
    const int q = blockIdx.x * 8 + (threadIdx.x >> 5);
    if (q >= NQ) return;
    const int lane = threadIdx.x & 31;
    const int h    = lane >> 2;
    const int ch0  = h * 32 + (lane & 3) * 8;

    // ATT: 8 logits (2 qu x 4 p) = 16B; OFF: 16 values = 32B
    uint4 attv = *(const uint4*)(ATT + (size_t)q * 64 + h * 8);
    uint4 offv[2];
    offv[0] = *(const uint4*)(OFF + (size_t)q * 128 + h * 16);
    offv[1] = *(const uint4*)(OFF + (size_t)q * 128 + h * 16 + 8);
    const __half2* ap = (const __half2*)&attv;

    float4 acc0 = make_float4(0.f, 0.f, 0.f, 0.f);
    float4 acc1 = make_float4(0.f, 0.f, 0.f, 0.f);
    #pragma unroll
    for (int qu = 0; qu < 2; qu++) {
        float2 a01 = __half22float2(ap[qu * 2 + 0]);
        float2 a23 = __half22float2(ap[qu * 2 + 1]);
        float l0 = a01.x, l1 = a01.y, l2 = a23.x, l3 = a23.y;
        float mx = fmaxf(fmaxf(l0, l1), fmaxf(l2, l3));
        float e0 = __expf(l0 - mx), e1 = __expf(l1 - mx);
        float e2 = __expf(l2 - mx), e3 = __expf(l3 - mx);
        float inv = 1.f / (e0 + e1 + e2 + e3);
        float w[4] = {e0 * inv, e1 * inv, e2 * inv, e3 * inv};

        float rpx = RP[(size_t)qu * NQ * 2 + (size_t)q * 2 + 0];
        float rpy = RP[(size_t)qu * NQ * 2 + (size_t)q * 2 + 1];
        const __half2* op = (const __half2*)&offv[qu];

        #pragma unroll
        for (int p = 0; p < 4; p++) {
            float2 oxy = __half22float2(op[p]);
            float x = (rpx + oxy.x * (1.f / GRID_W)) * GRID_W - 0.5f;
            float y = (rpy + oxy.y * (1.f / GRID_H)) * GRID_H - 0.5f;
            float x0f = floorf(x), y0f = floorf(y);
            float wx = x - x0f, wy = y - y0f;
            int x0 = (int)x0f, y0 = (int)y0f;
            float aw = w[p];
            float tw[4] = {aw * (1.f - wx) * (1.f - wy), aw * wx * (1.f - wy),
                           aw * (1.f - wx) * wy,          aw * wx * wy};
            int xs[4] = {x0, x0 + 1, x0,     x0 + 1};
            int ys[4] = {y0, y0,     y0 + 1, y0 + 1};
            #pragma unroll
            for (int t = 0; t < 4; t++) {
                int xx = xs[t], yy = ys[t];
                if (xx >= 0 && xx < GRID_W && yy >= 0 && yy < GRID_H) {
                    uint4 rv = __ldg((const uint4*)(V +
                        ((size_t)yy * GRID_W + xx) * 256 + ch0));
                    const __half2* hp = (const __half2*)&rv;
                    float2 f0 = __half22float2(hp[0]);
                    float2 f1 = __half22float2(hp[1]);
                    float2 f2 = __half22float2(hp[2]);
                    float2 f3 = __half22float2(hp[3]);
                    float wt = tw[t];
                    acc0.x += f0.x * wt; acc0.y += f0.y * wt;
                    acc0.z += f1.x * wt; acc0.w += f1.y * wt;
                    acc1.x += f2.x * wt; acc1.y += f2.y * wt;
                    acc1.z += f3.x * wt; acc1.w += f3.y * wt;
                }
            }
        }
    }
    acc0.x *= 0.5f; acc0.y *= 0.5f; acc0.z *= 0.5f; acc0.w *= 0.5f;
    acc1.x *= 0.5f; acc1.y *= 0.5f; acc1.z *= 0.5f; acc1.w *= 0.5f;
    __half* Sq = g_S16 + (size_t)q * 256;
    *(uint2*)&Sq[ch0]     = hi4h(acc0);
    *(uint2*)&Sq[ch0 + 4] = hi4h(acc1);
}

// ----------------------------------------------------------------------------
extern "C" void kernel_launch(void* const* d_in, const int* in_sizes, int n_in,
                              void* d_out, int out_size)
{
    const float* query  = (const float*)d_in[0];
    const float* qpos   = (const float*)d_in[1];
    const float* rp     = (const float*)d_in[2];
    const float* W_off  = (const float*)d_in[3];
    const float* b_off  = (const float*)d_in[4];
    const float* W_attn = (const float*)d_in[5];
    const float* b_attn = (const float*)d_in[6];
    const float* W_v    = (const float*)d_in[7];
    const float* b_v    = (const float*)d_in[8];
    const float* W_out  = (const float*)d_in[9];
    const float* b_out  = (const float*)d_in[10];
    float* out = (float*)d_out;

    __half *Aqc, *S16, *V16, *OFF, *ATT, *Wv, *Wcat, *Wout;
    cudaGetSymbolAddress((void**)&Aqc,  g_Aqc);
    cudaGetSymbolAddress((void**)&S16,  g_S16);
    cudaGetSymbolAddress((void**)&V16,  g_V16);
    cudaGetSymbolAddress((void**)&OFF,  g_OFF);
    cudaGetSymbolAddress((void**)&ATT,  g_ATT);
    cudaGetSymbolAddress((void**)&Wv,   g_Wv);
    cudaGetSymbolAddress((void**)&Wcat, g_Wcat);
    cudaGetSymbolAddress((void**)&Wout, g_Wout);

    const int SMEM = 3 * STAGE_BYTES;   // 73728
    cudaFuncSetAttribute(mma_gemm<0>, cudaFuncAttributeMaxDynamicSharedMemorySize, SMEM);
    cudaFuncSetAttribute(mma_gemm<1>, cudaFuncAttributeMaxDynamicSharedMemorySize, SMEM);

    const int MB = (NQ + 127) / 128;  // 176
    dim3 blk(256);

    // splits (weights + qcat) in one launch
    split_all<<<224 + NQ * 64 / 256, blk>>>(query, qpos, W_v, W_off, W_attn, W_out);

    // fused: value GEMM (y 0..3, K=256) + OFF (y 4..5) + ATT (y 6), all fp16 out
    mma_gemm<0><<<dim3(MB, 7), blk, SMEM>>>(Aqc, 512, Wv, Wcat,
                                            b_v, b_off, b_attn, nullptr,
                                            nullptr, V16, OFF, ATT, NQ);
    // sampling (all fp16 inputs) -> fp16 S
    sample_kernel<<<(NQ + 7) / 8, blk>>>(V16, OFF, ATT, rp);

    // out = S @ W_out + b_out + query  (K=256, fp32 out)
    mma_gemm<1><<<dim3(MB, 4), blk, SMEM>>>(S16, 256, Wout, nullptr,
                                            b_out, nullptr, nullptr, query,
                                            out, nullptr, nullptr, nullptr, NQ);
}